// round 4
// baseline (speedup 1.0000x reference)
#include <cuda_runtime.h>
#include <math.h>
#include <stdint.h>

#define B_    2
#define S_    2048
#define DM    1024
#define H_    16
#define DH    64
#define DFF   4096
#define MTOK  (B_*S_)      // 4096 token rows

// ---------------- scratch (device globals; no allocation) ----------------
__device__ float g_Q[MTOK*DM];
__device__ float g_K[MTOK*DM];
__device__ float g_V[MTOK*DM];
__device__ float g_att[MTOK*DM];
__device__ float g_x[MTOK*DM];
__device__ float g_h[(size_t)MTOK*DFF];

// ---------------- tf32 helpers -------------------------------------------
__device__ __forceinline__ float f2tf32(float x) {
    unsigned r;
    asm("cvt.rna.tf32.f32 %0, %1;" : "=r"(r) : "f"(x));
    return __uint_as_float(r);
}

__device__ __forceinline__ void mma_tf32(float c[4],
                                         unsigned a0, unsigned a1, unsigned a2, unsigned a3,
                                         unsigned b0, unsigned b1) {
    asm volatile("mma.sync.aligned.m16n8k8.row.col.f32.tf32.tf32.f32 "
                 "{%0,%1,%2,%3}, {%4,%5,%6,%7}, {%8,%9}, {%0,%1,%2,%3};"
                 : "+f"(c[0]), "+f"(c[1]), "+f"(c[2]), "+f"(c[3])
                 : "r"(a0), "r"(a1), "r"(a2), "r"(a3), "r"(b0), "r"(b1));
}

// ---------------- tensor-core GEMM (tf32), NT: C[m,n] = sum_k A[m,k]B[n,k]
// Tile 128x128, KC=16, double-buffered, fragment-major smem layout.
// 8 warps: 2(m) x 4(n), warp tile 64x32.
// EPI: 0 = +bias, 1 = gelu(+bias) exact, 2 = +bias + res
#define KC 16

template<int EPI>
__global__ __launch_bounds__(256)
void gemm_tc(const float* __restrict__ A, const float* __restrict__ Bm,
             const float* __restrict__ bias, float* __restrict__ C,
             const float* __restrict__ res, int M, int N, int K)
{
    // fragment-major storage:
    // A: idx(m16,kk,lane,e) = ((m16*2+kk)*32 + lane)*4 + e   (m16: 0..7, kk: 0..1)
    // B: idx(n8,lane,e)     = (n8*32 + lane)*4 + e           (n8: 0..15, e = kk*2+bi)
    __shared__ float Af[2][2048];
    __shared__ float Bf[2][2048];

    const int tid  = threadIdx.x;
    const int m0   = blockIdx.y * 128;
    const int n0   = blockIdx.x * 128;
    const int lane = tid & 31;
    const int w    = tid >> 5;
    const int wm   = (w >> 2) * 64;     // warp row offset (0 or 64)
    const int wn   = (w & 3) * 32;      // warp col offset
    const int m16b = (w >> 2) * 4;      // base m16 index
    const int n8b  = (w & 3) * 4;       // base n8 index
    const int g    = lane >> 2;
    const int t    = lane & 3;

    float acc[4][4][4];
    #pragma unroll
    for (int i = 0; i < 4; i++)
        #pragma unroll
        for (int j = 0; j < 4; j++)
            #pragma unroll
            for (int u = 0; u < 4; u++) acc[i][j][u] = 0.f;

    // staging: 2 float4 of A + 2 float4 of B per thread per chunk
    // lin = tid, tid+256 : row = lin>>2 (0..127), c = lin&3 (k cols 4c..4c+3)
    const int row0 = tid >> 2,          c0 = tid & 3;
    const int row1 = (tid + 256) >> 2,  c1 = (tid + 256) & 3;

    float4 ra[2], rb[2];
    const float* gA = A  + (size_t)m0 * K;
    const float* gB = Bm + (size_t)n0 * K;

    auto gload = [&](int k0) {
        ra[0] = *(const float4*)&gA[(size_t)row0 * K + k0 + c0 * 4];
        rb[0] = *(const float4*)&gB[(size_t)row0 * K + k0 + c0 * 4];
        ra[1] = *(const float4*)&gA[(size_t)row1 * K + k0 + c1 * 4];
        rb[1] = *(const float4*)&gB[(size_t)row1 * K + k0 + c1 * 4];
    };

    // scatter one float4 (row, c) into A-fragment layout
    auto stsA = [&](float* dst, int row, int c, float4 v) {
        const int m16   = row >> 4;
        const int rr    = row & 15;
        const int gg    = rr & 7;
        const int rhalf = rr >> 3;
        const int kk    = c >> 1;
        const int khalf = c & 1;
        const int e     = khalf * 2 + rhalf;
        float s[4] = {f2tf32(v.x), f2tf32(v.y), f2tf32(v.z), f2tf32(v.w)};
        const int base = ((m16 * 2 + kk) * 32 + gg * 4) * 4 + e;
        #pragma unroll
        for (int j = 0; j < 4; j++) dst[base + j * 4] = s[j];
    };
    // scatter one float4 (n, c) into B-fragment layout
    auto stsB = [&](float* dst, int n, int c, float4 v) {
        const int n8 = n >> 3;
        const int gg = n & 7;
        const int kk = c >> 1;
        const int bi = c & 1;
        const int e  = kk * 2 + bi;
        float s[4] = {f2tf32(v.x), f2tf32(v.y), f2tf32(v.z), f2tf32(v.w)};
        const int base = (n8 * 32 + gg * 4) * 4 + e;
        #pragma unroll
        for (int j = 0; j < 4; j++) dst[base + j * 4] = s[j];
    };

    auto sts = [&](int buf) {
        stsA(Af[buf], row0, c0, ra[0]);
        stsA(Af[buf], row1, c1, ra[1]);
        stsB(Bf[buf], row0, c0, rb[0]);
        stsB(Bf[buf], row1, c1, rb[1]);
    };

    auto compute = [&](int buf) {
        // B fragments: one float4 per n-tile covers both kk steps
        float4 bf[4];
        #pragma unroll
        for (int nt = 0; nt < 4; nt++)
            bf[nt] = *(const float4*)&Bf[buf][((n8b + nt) * 32 + lane) * 4];
        #pragma unroll
        for (int kk = 0; kk < 2; kk++) {
            float4 af[4];
            #pragma unroll
            for (int mt = 0; mt < 4; mt++)
                af[mt] = *(const float4*)&Af[buf][(((m16b + mt) * 2 + kk) * 32 + lane) * 4];
            #pragma unroll
            for (int mt = 0; mt < 4; mt++)
                #pragma unroll
                for (int nt = 0; nt < 4; nt++) {
                    const float b0 = kk ? bf[nt].z : bf[nt].x;
                    const float b1 = kk ? bf[nt].w : bf[nt].y;
                    mma_tf32(acc[mt][nt],
                             __float_as_uint(af[mt].x), __float_as_uint(af[mt].y),
                             __float_as_uint(af[mt].z), __float_as_uint(af[mt].w),
                             __float_as_uint(b0), __float_as_uint(b1));
                }
        }
    };

    const int NC = K / KC;
    gload(0);
    sts(0);
    __syncthreads();
    for (int c = 0; c < NC; c++) {
        if (c + 1 < NC) gload((c + 1) * KC);
        compute(c & 1);
        if (c + 1 < NC) sts((c + 1) & 1);
        __syncthreads();
    }

    // epilogue (c0,c1 = row g; c2,c3 = row g+8; cols 2t, 2t+1)
    #pragma unroll
    for (int mt = 0; mt < 4; mt++) {
        #pragma unroll
        for (int half = 0; half < 2; half++) {
            const int row = m0 + wm + mt * 16 + g + half * 8;
            #pragma unroll
            for (int nt = 0; nt < 4; nt++) {
                const int col = n0 + wn + nt * 8 + 2 * t;
                float v0 = acc[mt][nt][half * 2 + 0] + bias[col];
                float v1 = acc[mt][nt][half * 2 + 1] + bias[col + 1];
                if (EPI == 1) {
                    v0 = 0.5f * v0 * (1.0f + erff(v0 * 0.70710678118654752f));
                    v1 = 0.5f * v1 * (1.0f + erff(v1 * 0.70710678118654752f));
                } else if (EPI == 2) {
                    v0 += res[(size_t)row * N + col];
                    v1 += res[(size_t)row * N + col + 1];
                }
                float2 o; o.x = v0; o.y = v1;
                *(float2*)&C[(size_t)row * N + col] = o;
            }
        }
    }
}

// ---------------- causal flash attention (fp32, 2 threads per q row) -----
__global__ __launch_bounds__(256)
void attn_kernel(const float* __restrict__ Q, const float* __restrict__ K,
                 const float* __restrict__ V, float* __restrict__ O,
                 const int* __restrict__ use_mask)
{
    __shared__ float Ks[64 * 64];
    __shared__ float Vs[64 * 64];

    const int tid  = threadIdx.x;
    const int rowl = tid >> 1;
    const int half = tid & 1;
    const int wid  = tid >> 5;
    const int qb   = (gridDim.x - 1) - blockIdx.x;
    const int h    = blockIdx.y;
    const int b    = blockIdx.z;
    const int qi   = qb * 128 + rowl;
    const int causal = use_mask[0];

    float qreg[32];
    {
        const float4* qp = (const float4*)&Q[((size_t)(b * S_ + qi)) * DM + h * DH + half * 32];
        #pragma unroll
        for (int i = 0; i < 8; i++) {
            float4 f = qp[i];
            qreg[4*i+0] = f.x; qreg[4*i+1] = f.y; qreg[4*i+2] = f.z; qreg[4*i+3] = f.w;
        }
    }

    float m = -INFINITY, l = 0.f;
    float acc[32];
    #pragma unroll
    for (int d = 0; d < 32; d++) acc[d] = 0.f;

    const int kb_end = causal ? (qb * 2 + 2) : (S_ / 64);
    for (int kb = 0; kb < kb_end; kb++) {
        #pragma unroll
        for (int i = 0; i < 4; i++) {
            int lin = tid + i * 256;
            int row = lin >> 4;
            int c   = (lin & 15) * 4;
            size_t src = ((size_t)(b * S_ + kb * 64 + row)) * DM + h * DH + c;
            *(float4*)&Ks[row * 64 + c] = *(const float4*)&K[src];
            *(float4*)&Vs[row * 64 + c] = *(const float4*)&V[src];
        }
        __syncthreads();

        int jlim = 64, jub = 64;
        if (causal) {
            int rel = qi - kb * 64 + 1;
            jlim = rel < 64 ? rel : 64;
            int qimax = qb * 128 + wid * 16 + 15;
            int relw  = qimax - kb * 64 + 1;
            jub = relw < 64 ? relw : 64;
            if (jub < 0) jub = 0;
        }
        for (int j = 0; j < jub; j++) {
            const float4* kr = (const float4*)&Ks[j * 64 + half * 32];
            float s = 0.f;
            #pragma unroll
            for (int i = 0; i < 8; i++) {
                float4 f = kr[i];
                s = fmaf(qreg[4*i+0], f.x, s);
                s = fmaf(qreg[4*i+1], f.y, s);
                s = fmaf(qreg[4*i+2], f.z, s);
                s = fmaf(qreg[4*i+3], f.w, s);
            }
            s += __shfl_xor_sync(0xffffffffu, s, 1);
            s *= 0.125f;
            if (j < jlim) {
                if (s > m) {
                    float corr = __expf(m - s);
                    m = s;
                    l *= corr;
                    #pragma unroll
                    for (int d = 0; d < 32; d++) acc[d] *= corr;
                }
                float p = __expf(s - m);
                l += p;
                const float4* vr = (const float4*)&Vs[j * 64 + half * 32];
                #pragma unroll
                for (int i = 0; i < 8; i++) {
                    float4 f = vr[i];
                    acc[4*i+0] = fmaf(p, f.x, acc[4*i+0]);
                    acc[4*i+1] = fmaf(p, f.y, acc[4*i+1]);
                    acc[4*i+2] = fmaf(p, f.z, acc[4*i+2]);
                    acc[4*i+3] = fmaf(p, f.w, acc[4*i+3]);
                }
            }
        }
        __syncthreads();
    }

    const float inv = 1.f / l;
    float4* op = (float4*)&O[((size_t)(b * S_ + qi)) * DM + h * DH + half * 32];
    #pragma unroll
    for (int i = 0; i < 8; i++) {
        float4 f;
        f.x = acc[4*i+0] * inv; f.y = acc[4*i+1] * inv;
        f.z = acc[4*i+2] * inv; f.w = acc[4*i+3] * inv;
        op[i] = f;
    }
}

// ---------------- residual add + layernorm (one row per CTA) -------------
__global__ __launch_bounds__(256)
void ln_kernel(const float* __restrict__ att, const float* __restrict__ resid,
               const float* __restrict__ g, const float* __restrict__ bt,
               float* __restrict__ xout)
{
    const int row = blockIdx.x;
    const int tid = threadIdx.x;

    float4 a = *(const float4*)&att  [(size_t)row * DM + tid * 4];
    float4 r = *(const float4*)&resid[(size_t)row * DM + tid * 4];
    float4 v;
    v.x = a.x + r.x; v.y = a.y + r.y; v.z = a.z + r.z; v.w = a.w + r.w;

    float s1 = v.x + v.y + v.z + v.w;
    float s2 = v.x*v.x + v.y*v.y + v.z*v.z + v.w*v.w;

    __shared__ float sh1[8], sh2[8];
    #pragma unroll
    for (int o = 16; o > 0; o >>= 1) {
        s1 += __shfl_xor_sync(0xffffffffu, s1, o);
        s2 += __shfl_xor_sync(0xffffffffu, s2, o);
    }
    if ((tid & 31) == 0) { sh1[tid >> 5] = s1; sh2[tid >> 5] = s2; }
    __syncthreads();
    float t1 = 0.f, t2 = 0.f;
    #pragma unroll
    for (int i = 0; i < 8; i++) { t1 += sh1[i]; t2 += sh2[i]; }

    const float mu  = t1 * (1.0f / DM);
    const float var = t2 * (1.0f / DM) - mu * mu;
    const float rs  = rsqrtf(var + 1e-5f);

    float4 gg = *(const float4*)&g [tid * 4];
    float4 bb = *(const float4*)&bt[tid * 4];
    float4 o;
    o.x = (v.x - mu) * rs * gg.x + bb.x;
    o.y = (v.y - mu) * rs * gg.y + bb.y;
    o.z = (v.z - mu) * rs * gg.z + bb.z;
    o.w = (v.w - mu) * rs * gg.w + bb.w;
    *(float4*)&xout[(size_t)row * DM + tid * 4] = o;
}

// ---------------- launch ---------------------------------------------------
extern "C" void kernel_launch(void* const* d_in, const int* in_sizes, int n_in,
                              void* d_out, int out_size)
{
    const float* q    = (const float*)d_in[0];
    const float* k    = (const float*)d_in[1];
    const float* Wq   = (const float*)d_in[2];
    const float* bq   = (const float*)d_in[3];
    const float* Wk   = (const float*)d_in[4];
    const float* bk   = (const float*)d_in[5];
    const float* Wv   = (const float*)d_in[6];
    const float* bv   = (const float*)d_in[7];
    const float* W1   = (const float*)d_in[8];
    const float* b1   = (const float*)d_in[9];
    const float* W2   = (const float*)d_in[10];
    const float* b2   = (const float*)d_in[11];
    const float* ln_g = (const float*)d_in[12];
    const float* ln_b = (const float*)d_in[13];
    const int*   msk  = (const int*)d_in[14];

    float *Qb, *Kb, *Vb, *Ab, *Xb, *Hb;
    cudaGetSymbolAddress((void**)&Qb, g_Q);
    cudaGetSymbolAddress((void**)&Kb, g_K);
    cudaGetSymbolAddress((void**)&Vb, g_V);
    cudaGetSymbolAddress((void**)&Ab, g_att);
    cudaGetSymbolAddress((void**)&Xb, g_x);
    cudaGetSymbolAddress((void**)&Hb, g_h);

    // QKV projections: [4096,1024] @ [1024,1024]^T
    gemm_tc<0><<<dim3(DM / 128, MTOK / 128), 256>>>(q, Wq, bq, Qb, nullptr, MTOK, DM, DM);
    gemm_tc<0><<<dim3(DM / 128, MTOK / 128), 256>>>(k, Wk, bk, Kb, nullptr, MTOK, DM, DM);
    gemm_tc<0><<<dim3(DM / 128, MTOK / 128), 256>>>(k, Wv, bv, Vb, nullptr, MTOK, DM, DM);

    // causal attention
    attn_kernel<<<dim3(S_ / 128, H_, B_), 256>>>(Qb, Kb, Vb, Ab, msk);

    // residual + layernorm
    ln_kernel<<<MTOK, 256>>>(Ab, q, ln_g, ln_b, Xb);

    // FFN: gelu(x @ W1^T + b1) @ W2^T + b2 + x
    gemm_tc<1><<<dim3(DFF / 128, MTOK / 128), 256>>>(Xb, W1, b1, Hb, nullptr, MTOK, DFF, DM);
    gemm_tc<2><<<dim3(DM / 128, MTOK / 128), 256>>>(Hb, W2, b2, (float*)d_out, Xb, MTOK, DM, DFF);
}

// round 5
// speedup vs baseline: 2.1196x; 2.1196x over previous
#include <cuda_runtime.h>
#include <math.h>
#include <stdint.h>

#define B_    2
#define S_    2048
#define DM    1024
#define H_    16
#define DH    64
#define DFF   4096
#define MTOK  (B_*S_)      // 4096 token rows

// ---------------- scratch (device globals; no allocation) ----------------
__device__ float g_Q[MTOK*DM];
__device__ float g_K[MTOK*DM];
__device__ float g_V[MTOK*DM];
__device__ float g_att[MTOK*DM];
__device__ float g_x[MTOK*DM];
__device__ float g_h[(size_t)MTOK*DFF];

// ---------------- tf32 helpers -------------------------------------------
__device__ __forceinline__ float f2tf32(float x) {
    unsigned r;
    asm("cvt.rna.tf32.f32 %0, %1;" : "=r"(r) : "f"(x));
    return __uint_as_float(r);
}

__device__ __forceinline__ void mma_tf32(float c[4],
                                         unsigned a0, unsigned a1, unsigned a2, unsigned a3,
                                         unsigned b0, unsigned b1) {
    asm volatile("mma.sync.aligned.m16n8k8.row.col.f32.tf32.tf32.f32 "
                 "{%0,%1,%2,%3}, {%4,%5,%6,%7}, {%8,%9}, {%0,%1,%2,%3};"
                 : "+f"(c[0]), "+f"(c[1]), "+f"(c[2]), "+f"(c[3])
                 : "r"(a0), "r"(a1), "r"(a2), "r"(a3), "r"(b0), "r"(b1));
}

// ---------------- tensor-core GEMM (tf32), NT (R2 version, known-good) ---
#define KC 16
#define LDS_PITCH 20

template<int EPI>
__global__ __launch_bounds__(256)
void gemm_tc(const float* __restrict__ A, const float* __restrict__ Bm,
             const float* __restrict__ bias, float* __restrict__ C,
             const float* __restrict__ res, int M, int N, int K)
{
    __shared__ float As[2][128 * LDS_PITCH];
    __shared__ float Bs[2][128 * LDS_PITCH];

    const int tid  = threadIdx.x;
    const int m0   = blockIdx.y * 128;
    const int n0   = blockIdx.x * 128;
    const int lane = tid & 31;
    const int w    = tid >> 5;
    const int wm   = (w >> 2) * 64;
    const int wn   = (w & 3) * 32;
    const int g    = lane >> 2;
    const int t    = lane & 3;

    float acc[4][4][4];
    #pragma unroll
    for (int i = 0; i < 4; i++)
        #pragma unroll
        for (int j = 0; j < 4; j++)
            #pragma unroll
            for (int u = 0; u < 4; u++) acc[i][j][u] = 0.f;

    float4 ra[2], rb[2];
    const int srow0 = tid >> 2;
    const int sc40  = tid & 3;
    const int srow1 = (tid + 256) >> 2;
    const int sc41  = (tid + 256) & 3;

    auto gload = [&](int k0) {
        ra[0] = *(const float4*)&A [(size_t)(m0 + srow0) * K + k0 + sc40 * 4];
        rb[0] = *(const float4*)&Bm[(size_t)(n0 + srow0) * K + k0 + sc40 * 4];
        ra[1] = *(const float4*)&A [(size_t)(m0 + srow1) * K + k0 + sc41 * 4];
        rb[1] = *(const float4*)&Bm[(size_t)(n0 + srow1) * K + k0 + sc41 * 4];
    };
    auto sts = [&](int buf) {
        float4 v;
        v.x = f2tf32(ra[0].x); v.y = f2tf32(ra[0].y); v.z = f2tf32(ra[0].z); v.w = f2tf32(ra[0].w);
        *(float4*)&As[buf][srow0 * LDS_PITCH + sc40 * 4] = v;
        v.x = f2tf32(rb[0].x); v.y = f2tf32(rb[0].y); v.z = f2tf32(rb[0].z); v.w = f2tf32(rb[0].w);
        *(float4*)&Bs[buf][srow0 * LDS_PITCH + sc40 * 4] = v;
        v.x = f2tf32(ra[1].x); v.y = f2tf32(ra[1].y); v.z = f2tf32(ra[1].z); v.w = f2tf32(ra[1].w);
        *(float4*)&As[buf][srow1 * LDS_PITCH + sc41 * 4] = v;
        v.x = f2tf32(rb[1].x); v.y = f2tf32(rb[1].y); v.z = f2tf32(rb[1].z); v.w = f2tf32(rb[1].w);
        *(float4*)&Bs[buf][srow1 * LDS_PITCH + sc41 * 4] = v;
    };
    auto compute = [&](int buf) {
        #pragma unroll
        for (int kk = 0; kk < KC; kk += 8) {
            unsigned af[4][4], bf[4][2];
            #pragma unroll
            for (int mt = 0; mt < 4; mt++) {
                int r = wm + mt * 16 + g;
                af[mt][0] = __float_as_uint(As[buf][(r    ) * LDS_PITCH + kk + t    ]);
                af[mt][1] = __float_as_uint(As[buf][(r + 8) * LDS_PITCH + kk + t    ]);
                af[mt][2] = __float_as_uint(As[buf][(r    ) * LDS_PITCH + kk + t + 4]);
                af[mt][3] = __float_as_uint(As[buf][(r + 8) * LDS_PITCH + kk + t + 4]);
            }
            #pragma unroll
            for (int nt = 0; nt < 4; nt++) {
                int r = wn + nt * 8 + g;
                bf[nt][0] = __float_as_uint(Bs[buf][r * LDS_PITCH + kk + t    ]);
                bf[nt][1] = __float_as_uint(Bs[buf][r * LDS_PITCH + kk + t + 4]);
            }
            #pragma unroll
            for (int mt = 0; mt < 4; mt++)
                #pragma unroll
                for (int nt = 0; nt < 4; nt++)
                    mma_tf32(acc[mt][nt], af[mt][0], af[mt][1], af[mt][2], af[mt][3],
                             bf[nt][0], bf[nt][1]);
        }
    };

    const int NC = K / KC;
    gload(0);
    sts(0);
    __syncthreads();
    for (int c = 0; c < NC; c++) {
        if (c + 1 < NC) gload((c + 1) * KC);
        compute(c & 1);
        if (c + 1 < NC) sts((c + 1) & 1);
        __syncthreads();
    }

    #pragma unroll
    for (int mt = 0; mt < 4; mt++) {
        #pragma unroll
        for (int half = 0; half < 2; half++) {
            const int row = m0 + wm + mt * 16 + g + half * 8;
            #pragma unroll
            for (int nt = 0; nt < 4; nt++) {
                const int col = n0 + wn + nt * 8 + 2 * t;
                float v0 = acc[mt][nt][half * 2 + 0] + bias[col];
                float v1 = acc[mt][nt][half * 2 + 1] + bias[col + 1];
                if (EPI == 1) {
                    v0 = 0.5f * v0 * (1.0f + erff(v0 * 0.70710678118654752f));
                    v1 = 0.5f * v1 * (1.0f + erff(v1 * 0.70710678118654752f));
                } else if (EPI == 2) {
                    v0 += res[(size_t)row * N + col];
                    v1 += res[(size_t)row * N + col + 1];
                }
                float2 o; o.x = v0; o.y = v1;
                *(float2*)&C[(size_t)row * N + col] = o;
            }
        }
    }
}

// ---------------- tensor-core causal flash attention (tf32 mma) ----------
// CTA: 128 q rows, 8 warps (16 rows each). kv tiles of 64.
__global__ __launch_bounds__(256)
void attn_tc(const float* __restrict__ Q, const float* __restrict__ K,
             const float* __restrict__ V, float* __restrict__ O,
             const int* __restrict__ use_mask)
{
    __shared__ float Ks[64 * 68];
    __shared__ float Vs[64 * 68];

    const int tid  = threadIdx.x;
    const int lane = tid & 31;
    const int w    = tid >> 5;
    const int g    = lane >> 2;
    const int t    = lane & 3;
    const int qb   = (gridDim.x - 1) - blockIdx.x;   // heavy q-blocks first
    const int h    = blockIdx.y;
    const int b    = blockIdx.z;
    const int q0   = qb * 128;
    const int causal = use_mask[0];
    const int row0 = q0 + w * 16 + g;                // rows row0 and row0+8

    // Q fragments (A-layout), resident for whole kernel
    unsigned qf[8][4];
    {
        const float* qp  = Q + ((size_t)(b * S_ + row0)) * DM + h * DH;
        const float* qp8 = qp + 8 * DM;
        #pragma unroll
        for (int kk = 0; kk < 8; kk++) {
            qf[kk][0] = __float_as_uint(f2tf32(qp [kk * 8 + t    ]));
            qf[kk][1] = __float_as_uint(f2tf32(qp8[kk * 8 + t    ]));
            qf[kk][2] = __float_as_uint(f2tf32(qp [kk * 8 + t + 4]));
            qf[kk][3] = __float_as_uint(f2tf32(qp8[kk * 8 + t + 4]));
        }
    }

    float m0 = -INFINITY, m1 = -INFINITY, l0 = 0.f, l1 = 0.f;
    float oacc[8][4];
    #pragma unroll
    for (int nt = 0; nt < 8; nt++)
        #pragma unroll
        for (int u = 0; u < 4; u++) oacc[nt][u] = 0.f;

    const int nkb = causal ? (qb * 2 + 2) : (S_ / 64);

    // staging: slot s = tid + i*256 -> row = s>>4, col4 = (s&15)*4
    const int sr = tid >> 4;
    const int sc = (tid & 15) * 4;
    float4 pk[4], pv[4];
    {
        #pragma unroll
        for (int i = 0; i < 4; i++) {
            size_t src = ((size_t)(b * S_ + sr + i * 16)) * DM + h * DH + sc;
            pk[i] = *(const float4*)&K[src];
            pv[i] = *(const float4*)&V[src];
        }
    }

    for (int kb = 0; kb < nkb; kb++) {
        __syncthreads();   // prior tile fully consumed
        #pragma unroll
        for (int i = 0; i < 4; i++) {
            const int r = sr + i * 16;
            float4 v = pk[i];
            v.x = f2tf32(v.x); v.y = f2tf32(v.y); v.z = f2tf32(v.z); v.w = f2tf32(v.w);
            *(float4*)&Ks[r * 68 + sc] = v;
            v = pv[i];
            v.x = f2tf32(v.x); v.y = f2tf32(v.y); v.z = f2tf32(v.z); v.w = f2tf32(v.w);
            *(float4*)&Vs[r * 68 + sc] = v;
        }
        __syncthreads();

        // prefetch next tile
        if (kb + 1 < nkb) {
            #pragma unroll
            for (int i = 0; i < 4; i++) {
                size_t src = ((size_t)(b * S_ + (kb + 1) * 64 + sr + i * 16)) * DM + h * DH + sc;
                pk[i] = *(const float4*)&K[src];
                pv[i] = *(const float4*)&V[src];
            }
        }

        // ---- S = Q K^T (16x64 per warp) ----
        float sa[8][4];
        #pragma unroll
        for (int nt = 0; nt < 8; nt++)
            #pragma unroll
            for (int u = 0; u < 4; u++) sa[nt][u] = 0.f;

        #pragma unroll
        for (int kk = 0; kk < 8; kk++) {
            unsigned bf[8][2];
            #pragma unroll
            for (int nt = 0; nt < 8; nt++) {
                bf[nt][0] = __float_as_uint(Ks[(nt * 8 + g) * 68 + kk * 8 + t    ]);
                bf[nt][1] = __float_as_uint(Ks[(nt * 8 + g) * 68 + kk * 8 + t + 4]);
            }
            #pragma unroll
            for (int nt = 0; nt < 8; nt++)
                mma_tf32(sa[nt], qf[kk][0], qf[kk][1], qf[kk][2], qf[kk][3],
                         bf[nt][0], bf[nt][1]);
        }

        // ---- softmax (registers) ----
        const bool mask_tile = causal && (kb >= qb * 2);
        float smax0 = -INFINITY, smax1 = -INFINITY;
        #pragma unroll
        for (int nt = 0; nt < 8; nt++) {
            const int col = kb * 64 + nt * 8 + 2 * t;
            sa[nt][0] *= 0.125f; sa[nt][1] *= 0.125f;
            sa[nt][2] *= 0.125f; sa[nt][3] *= 0.125f;
            if (mask_tile) {
                if (col     > row0)     sa[nt][0] = -1e9f;
                if (col + 1 > row0)     sa[nt][1] = -1e9f;
                if (col     > row0 + 8) sa[nt][2] = -1e9f;
                if (col + 1 > row0 + 8) sa[nt][3] = -1e9f;
            }
            smax0 = fmaxf(smax0, fmaxf(sa[nt][0], sa[nt][1]));
            smax1 = fmaxf(smax1, fmaxf(sa[nt][2], sa[nt][3]));
        }
        smax0 = fmaxf(smax0, __shfl_xor_sync(0xffffffffu, smax0, 1));
        smax0 = fmaxf(smax0, __shfl_xor_sync(0xffffffffu, smax0, 2));
        smax1 = fmaxf(smax1, __shfl_xor_sync(0xffffffffu, smax1, 1));
        smax1 = fmaxf(smax1, __shfl_xor_sync(0xffffffffu, smax1, 2));

        const float m0n = fmaxf(m0, smax0);
        const float m1n = fmaxf(m1, smax1);
        const float cr0 = __expf(m0 - m0n);
        const float cr1 = __expf(m1 - m1n);
        m0 = m0n; m1 = m1n;

        float ls0 = 0.f, ls1 = 0.f;
        #pragma unroll
        for (int nt = 0; nt < 8; nt++) {
            sa[nt][0] = __expf(sa[nt][0] - m0n);
            sa[nt][1] = __expf(sa[nt][1] - m0n);
            sa[nt][2] = __expf(sa[nt][2] - m1n);
            sa[nt][3] = __expf(sa[nt][3] - m1n);
            ls0 += sa[nt][0] + sa[nt][1];
            ls1 += sa[nt][2] + sa[nt][3];
        }
        ls0 += __shfl_xor_sync(0xffffffffu, ls0, 1);
        ls0 += __shfl_xor_sync(0xffffffffu, ls0, 2);
        ls1 += __shfl_xor_sync(0xffffffffu, ls1, 1);
        ls1 += __shfl_xor_sync(0xffffffffu, ls1, 2);
        l0 = l0 * cr0 + ls0;
        l1 = l1 * cr1 + ls1;

        #pragma unroll
        for (int nt = 0; nt < 8; nt++) {
            oacc[nt][0] *= cr0; oacc[nt][1] *= cr0;
            oacc[nt][2] *= cr1; oacc[nt][3] *= cr1;
        }

        // ---- O += P V : shfl-convert P (C-layout -> A-layout) ----
        const int src0 = (lane & 28) | (t >> 1);
        const int src1 = src0 + 2;
        const bool odd = t & 1;
        #pragma unroll
        for (int j = 0; j < 8; j++) {
            float p0a = __shfl_sync(0xffffffffu, sa[j][0], src0);
            float p1a = __shfl_sync(0xffffffffu, sa[j][1], src0);
            float p0b = __shfl_sync(0xffffffffu, sa[j][0], src1);
            float p1b = __shfl_sync(0xffffffffu, sa[j][1], src1);
            float r0a = __shfl_sync(0xffffffffu, sa[j][2], src0);
            float r1a = __shfl_sync(0xffffffffu, sa[j][3], src0);
            float r0b = __shfl_sync(0xffffffffu, sa[j][2], src1);
            float r1b = __shfl_sync(0xffffffffu, sa[j][3], src1);
            const unsigned a0 = __float_as_uint(f2tf32(odd ? p1a : p0a));
            const unsigned a1 = __float_as_uint(f2tf32(odd ? r1a : r0a));
            const unsigned a2 = __float_as_uint(f2tf32(odd ? p1b : p0b));
            const unsigned a3 = __float_as_uint(f2tf32(odd ? r1b : r0b));
            #pragma unroll
            for (int nt = 0; nt < 8; nt++) {
                const unsigned b0 = __float_as_uint(Vs[(j * 8 + t    ) * 68 + nt * 8 + g]);
                const unsigned b1 = __float_as_uint(Vs[(j * 8 + t + 4) * 68 + nt * 8 + g]);
                mma_tf32(oacc[nt], a0, a1, a2, a3, b0, b1);
            }
        }
    }

    const float inv0 = 1.f / l0;
    const float inv1 = 1.f / l1;
    float* op = O + ((size_t)(b * S_ + row0)) * DM + h * DH;
    #pragma unroll
    for (int nt = 0; nt < 8; nt++) {
        float2 v;
        v.x = oacc[nt][0] * inv0; v.y = oacc[nt][1] * inv0;
        *(float2*)&op[nt * 8 + 2 * t] = v;
        v.x = oacc[nt][2] * inv1; v.y = oacc[nt][3] * inv1;
        *(float2*)&op[(size_t)8 * DM + nt * 8 + 2 * t] = v;
    }
}

// ---------------- residual add + layernorm (one row per CTA) -------------
__global__ __launch_bounds__(256)
void ln_kernel(const float* __restrict__ att, const float* __restrict__ resid,
               const float* __restrict__ g, const float* __restrict__ bt,
               float* __restrict__ xout)
{
    const int row = blockIdx.x;
    const int tid = threadIdx.x;

    float4 a = *(const float4*)&att  [(size_t)row * DM + tid * 4];
    float4 r = *(const float4*)&resid[(size_t)row * DM + tid * 4];
    float4 v;
    v.x = a.x + r.x; v.y = a.y + r.y; v.z = a.z + r.z; v.w = a.w + r.w;

    float s1 = v.x + v.y + v.z + v.w;
    float s2 = v.x*v.x + v.y*v.y + v.z*v.z + v.w*v.w;

    __shared__ float sh1[8], sh2[8];
    #pragma unroll
    for (int o = 16; o > 0; o >>= 1) {
        s1 += __shfl_xor_sync(0xffffffffu, s1, o);
        s2 += __shfl_xor_sync(0xffffffffu, s2, o);
    }
    if ((tid & 31) == 0) { sh1[tid >> 5] = s1; sh2[tid >> 5] = s2; }
    __syncthreads();
    float t1 = 0.f, t2 = 0.f;
    #pragma unroll
    for (int i = 0; i < 8; i++) { t1 += sh1[i]; t2 += sh2[i]; }

    const float mu  = t1 * (1.0f / DM);
    const float var = t2 * (1.0f / DM) - mu * mu;
    const float rs  = rsqrtf(var + 1e-5f);

    float4 gg = *(const float4*)&g [tid * 4];
    float4 bb = *(const float4*)&bt[tid * 4];
    float4 o;
    o.x = (v.x - mu) * rs * gg.x + bb.x;
    o.y = (v.y - mu) * rs * gg.y + bb.y;
    o.z = (v.z - mu) * rs * gg.z + bb.z;
    o.w = (v.w - mu) * rs * gg.w + bb.w;
    *(float4*)&xout[(size_t)row * DM + tid * 4] = o;
}

// ---------------- launch ---------------------------------------------------
extern "C" void kernel_launch(void* const* d_in, const int* in_sizes, int n_in,
                              void* d_out, int out_size)
{
    const float* q    = (const float*)d_in[0];
    const float* k    = (const float*)d_in[1];
    const float* Wq   = (const float*)d_in[2];
    const float* bq   = (const float*)d_in[3];
    const float* Wk   = (const float*)d_in[4];
    const float* bk   = (const float*)d_in[5];
    const float* Wv   = (const float*)d_in[6];
    const float* bv   = (const float*)d_in[7];
    const float* W1   = (const float*)d_in[8];
    const float* b1   = (const float*)d_in[9];
    const float* W2   = (const float*)d_in[10];
    const float* b2   = (const float*)d_in[11];
    const float* ln_g = (const float*)d_in[12];
    const float* ln_b = (const float*)d_in[13];
    const int*   msk  = (const int*)d_in[14];

    float *Qb, *Kb, *Vb, *Ab, *Xb, *Hb;
    cudaGetSymbolAddress((void**)&Qb, g_Q);
    cudaGetSymbolAddress((void**)&Kb, g_K);
    cudaGetSymbolAddress((void**)&Vb, g_V);
    cudaGetSymbolAddress((void**)&Ab, g_att);
    cudaGetSymbolAddress((void**)&Xb, g_x);
    cudaGetSymbolAddress((void**)&Hb, g_h);

    // QKV projections: [4096,1024] @ [1024,1024]^T
    gemm_tc<0><<<dim3(DM / 128, MTOK / 128), 256>>>(q, Wq, bq, Qb, nullptr, MTOK, DM, DM);
    gemm_tc<0><<<dim3(DM / 128, MTOK / 128), 256>>>(k, Wk, bk, Kb, nullptr, MTOK, DM, DM);
    gemm_tc<0><<<dim3(DM / 128, MTOK / 128), 256>>>(k, Wv, bv, Vb, nullptr, MTOK, DM, DM);

    // causal attention (tensor cores)
    attn_tc<<<dim3(S_ / 128, H_, B_), 256>>>(Qb, Kb, Vb, Ab, msk);

    // residual + layernorm
    ln_kernel<<<MTOK, 256>>>(Ab, q, ln_g, ln_b, Xb);

    // FFN: gelu(x @ W1^T + b1) @ W2^T + b2 + x
    gemm_tc<1><<<dim3(DFF / 128, MTOK / 128), 256>>>(Xb, W1, b1, Hb, nullptr, MTOK, DFF, DM);
    gemm_tc<2><<<dim3(DM / 128, MTOK / 128), 256>>>(Hb, W2, b2, (float*)d_out, Xb, MTOK, DM, DFF);
}

// round 6
// speedup vs baseline: 2.9275x; 1.3812x over previous
#include <cuda_runtime.h>
#include <cuda_fp16.h>
#include <math.h>
#include <stdint.h>

#define B_    2
#define S_    2048
#define DM    1024
#define H_    16
#define DH    64
#define DFF   4096
#define MTOK  (B_*S_)      // 4096 token rows

// ---------------- scratch (device globals; no allocation) ----------------
__device__ float g_Q[MTOK*DM];
__device__ float g_K[MTOK*DM];
__device__ float g_V[MTOK*DM];
__device__ float g_att[MTOK*DM];
__device__ float g_x[MTOK*DM];
__device__ float g_h[(size_t)MTOK*DFF];

// ---------------- helpers -------------------------------------------------
__device__ __forceinline__ float f2tf32(float x) {
    unsigned r;
    asm("cvt.rna.tf32.f32 %0, %1;" : "=r"(r) : "f"(x));
    return __uint_as_float(r);
}

__device__ __forceinline__ void mma_tf32(float c[4],
                                         unsigned a0, unsigned a1, unsigned a2, unsigned a3,
                                         unsigned b0, unsigned b1) {
    asm volatile("mma.sync.aligned.m16n8k8.row.col.f32.tf32.tf32.f32 "
                 "{%0,%1,%2,%3}, {%4,%5,%6,%7}, {%8,%9}, {%0,%1,%2,%3};"
                 : "+f"(c[0]), "+f"(c[1]), "+f"(c[2]), "+f"(c[3])
                 : "r"(a0), "r"(a1), "r"(a2), "r"(a3), "r"(b0), "r"(b1));
}

__device__ __forceinline__ void mma_f16(float c[4],
                                        unsigned a0, unsigned a1, unsigned a2, unsigned a3,
                                        unsigned b0, unsigned b1) {
    asm volatile("mma.sync.aligned.m16n8k16.row.col.f32.f16.f16.f32 "
                 "{%0,%1,%2,%3}, {%4,%5,%6,%7}, {%8,%9}, {%0,%1,%2,%3};"
                 : "+f"(c[0]), "+f"(c[1]), "+f"(c[2]), "+f"(c[3])
                 : "r"(a0), "r"(a1), "r"(a2), "r"(a3), "r"(b0), "r"(b1));
}

#define LDSM_X4(r0, r1, r2, r3, addr) \
    asm volatile("ldmatrix.sync.aligned.m8n8.x4.shared.b16 {%0,%1,%2,%3}, [%4];" \
                 : "=r"(r0), "=r"(r1), "=r"(r2), "=r"(r3) : "r"(addr))

// ---------------- fp16 tensor-core GEMM, NT: C[m,n] = sum_k A[m,k]B[n,k] --
// CTA tile 128x128, KC=32, double-buffered fp16 smem (pitch 40 halves),
// 8 warps 2(m)x4(n), warp tile 64x32, ldmatrix fragment loads.
// EPI: 0 = +bias, 1 = gelu(+bias) exact, 2 = +bias + res
#define KCH 32
#define HP  40            // half pitch: 80 bytes = 5*16 -> conflict-free ldmatrix

template<int EPI>
__global__ __launch_bounds__(256)
void gemm_h(const float* __restrict__ A, const float* __restrict__ Bm,
            const float* __restrict__ bias, float* __restrict__ C,
            const float* __restrict__ res, int M, int N, int K)
{
    __shared__ __half As[2][128 * HP];
    __shared__ __half Bs[2][128 * HP];

    const int tid  = threadIdx.x;
    const int m0   = blockIdx.y * 128;
    const int n0   = blockIdx.x * 128;
    const int lane = tid & 31;
    const int w    = tid >> 5;
    const int wm   = (w >> 2) * 64;
    const int wn   = (w & 3) * 32;
    const int g    = lane >> 2;
    const int t    = lane & 3;

    float acc[4][4][4];
    #pragma unroll
    for (int i = 0; i < 4; i++)
        #pragma unroll
        for (int j = 0; j < 4; j++)
            #pragma unroll
            for (int u = 0; u < 4; u++) acc[i][j][u] = 0.f;

    const uint32_t sA = (uint32_t)__cvta_generic_to_shared(&As[0][0]);
    const uint32_t sB = (uint32_t)__cvta_generic_to_shared(&Bs[0][0]);
    const uint32_t BUFO = 128 * HP * 2;   // bytes per buffer

    // ldmatrix per-thread base addresses (bytes)
    const uint32_t a_base = sA + (((uint32_t)(wm + (lane & 15))) * HP + ((lane >> 4) * 8)) * 2;
    const uint32_t b_base = sB + (((uint32_t)(wn + (lane & 7)))  * HP + ((lane >> 3) * 8)) * 2;

    // staging slots: s = tid + i*256 -> row = s>>3, g4 = s&7 (float4 each)
    float4 ra[4], rb[4];
    const int srow = tid >> 3;
    const int sg4  = tid & 7;

    auto gload = [&](int k0) {
        #pragma unroll
        for (int i = 0; i < 4; i++) {
            const int row = srow + i * 32;
            ra[i] = *(const float4*)&A [(size_t)(m0 + row) * K + k0 + sg4 * 4];
            rb[i] = *(const float4*)&Bm[(size_t)(n0 + row) * K + k0 + sg4 * 4];
        }
    };
    auto sts = [&](int buf) {
        #pragma unroll
        for (int i = 0; i < 4; i++) {
            const int row = srow + i * 32;
            const int idx = row * HP + sg4 * 4;
            __half2 h0 = __floats2half2_rn(ra[i].x, ra[i].y);
            __half2 h1 = __floats2half2_rn(ra[i].z, ra[i].w);
            *(__half2*)&As[buf][idx]     = h0;
            *(__half2*)&As[buf][idx + 2] = h1;
            h0 = __floats2half2_rn(rb[i].x, rb[i].y);
            h1 = __floats2half2_rn(rb[i].z, rb[i].w);
            *(__half2*)&Bs[buf][idx]     = h0;
            *(__half2*)&Bs[buf][idx + 2] = h1;
        }
    };
    auto compute = [&](int buf) {
        const uint32_t bo = buf ? BUFO : 0;
        unsigned bq[4][4];
        #pragma unroll
        for (int nt = 0; nt < 4; nt++)
            LDSM_X4(bq[nt][0], bq[nt][1], bq[nt][2], bq[nt][3],
                    b_base + bo + nt * (8 * HP * 2));
        #pragma unroll
        for (int kh = 0; kh < 2; kh++) {
            unsigned aq[4][4];
            #pragma unroll
            for (int mt = 0; mt < 4; mt++)
                LDSM_X4(aq[mt][0], aq[mt][1], aq[mt][2], aq[mt][3],
                        a_base + bo + mt * (16 * HP * 2) + kh * 32);
            #pragma unroll
            for (int mt = 0; mt < 4; mt++)
                #pragma unroll
                for (int nt = 0; nt < 4; nt++)
                    mma_f16(acc[mt][nt], aq[mt][0], aq[mt][1], aq[mt][2], aq[mt][3],
                            bq[nt][kh * 2], bq[nt][kh * 2 + 1]);
        }
    };

    const int NC = K / KCH;
    gload(0);
    sts(0);
    __syncthreads();
    for (int c = 0; c < NC; c++) {
        if (c + 1 < NC) gload((c + 1) * KCH);
        compute(c & 1);
        if (c + 1 < NC) sts((c + 1) & 1);
        __syncthreads();
    }

    // epilogue (same C fragment layout as m16n8k8)
    #pragma unroll
    for (int mt = 0; mt < 4; mt++) {
        #pragma unroll
        for (int half = 0; half < 2; half++) {
            const int row = m0 + wm + mt * 16 + g + half * 8;
            #pragma unroll
            for (int nt = 0; nt < 4; nt++) {
                const int col = n0 + wn + nt * 8 + 2 * t;
                float v0 = acc[mt][nt][half * 2 + 0] + bias[col];
                float v1 = acc[mt][nt][half * 2 + 1] + bias[col + 1];
                if (EPI == 1) {
                    v0 = 0.5f * v0 * (1.0f + erff(v0 * 0.70710678118654752f));
                    v1 = 0.5f * v1 * (1.0f + erff(v1 * 0.70710678118654752f));
                } else if (EPI == 2) {
                    v0 += res[(size_t)row * N + col];
                    v1 += res[(size_t)row * N + col + 1];
                }
                float2 o; o.x = v0; o.y = v1;
                *(float2*)&C[(size_t)row * N + col] = o;
            }
        }
    }
}

// ---------------- tensor-core causal flash attention (tf32 mma) ----------
__global__ __launch_bounds__(256)
void attn_tc(const float* __restrict__ Q, const float* __restrict__ K,
             const float* __restrict__ V, float* __restrict__ O,
             const int* __restrict__ use_mask)
{
    __shared__ float Ks[64 * 68];
    __shared__ float Vs[64 * 68];

    const int tid  = threadIdx.x;
    const int lane = tid & 31;
    const int w    = tid >> 5;
    const int g    = lane >> 2;
    const int t    = lane & 3;
    const int qb   = (gridDim.x - 1) - blockIdx.x;
    const int h    = blockIdx.y;
    const int b    = blockIdx.z;
    const int q0   = qb * 128;
    const int causal = use_mask[0];
    const int row0 = q0 + w * 16 + g;

    unsigned qf[8][4];
    {
        const float* qp  = Q + ((size_t)(b * S_ + row0)) * DM + h * DH;
        const float* qp8 = qp + 8 * DM;
        #pragma unroll
        for (int kk = 0; kk < 8; kk++) {
            qf[kk][0] = __float_as_uint(f2tf32(qp [kk * 8 + t    ]));
            qf[kk][1] = __float_as_uint(f2tf32(qp8[kk * 8 + t    ]));
            qf[kk][2] = __float_as_uint(f2tf32(qp [kk * 8 + t + 4]));
            qf[kk][3] = __float_as_uint(f2tf32(qp8[kk * 8 + t + 4]));
        }
    }

    float m0 = -INFINITY, m1 = -INFINITY, l0 = 0.f, l1 = 0.f;
    float oacc[8][4];
    #pragma unroll
    for (int nt = 0; nt < 8; nt++)
        #pragma unroll
        for (int u = 0; u < 4; u++) oacc[nt][u] = 0.f;

    const int nkb = causal ? (qb * 2 + 2) : (S_ / 64);

    const int sr = tid >> 4;
    const int sc = (tid & 15) * 4;
    float4 pk[4], pv[4];
    {
        #pragma unroll
        for (int i = 0; i < 4; i++) {
            size_t src = ((size_t)(b * S_ + sr + i * 16)) * DM + h * DH + sc;
            pk[i] = *(const float4*)&K[src];
            pv[i] = *(const float4*)&V[src];
        }
    }

    for (int kb = 0; kb < nkb; kb++) {
        __syncthreads();
        #pragma unroll
        for (int i = 0; i < 4; i++) {
            const int r = sr + i * 16;
            float4 v = pk[i];
            v.x = f2tf32(v.x); v.y = f2tf32(v.y); v.z = f2tf32(v.z); v.w = f2tf32(v.w);
            *(float4*)&Ks[r * 68 + sc] = v;
            v = pv[i];
            v.x = f2tf32(v.x); v.y = f2tf32(v.y); v.z = f2tf32(v.z); v.w = f2tf32(v.w);
            *(float4*)&Vs[r * 68 + sc] = v;
        }
        __syncthreads();

        if (kb + 1 < nkb) {
            #pragma unroll
            for (int i = 0; i < 4; i++) {
                size_t src = ((size_t)(b * S_ + (kb + 1) * 64 + sr + i * 16)) * DM + h * DH + sc;
                pk[i] = *(const float4*)&K[src];
                pv[i] = *(const float4*)&V[src];
            }
        }

        float sa[8][4];
        #pragma unroll
        for (int nt = 0; nt < 8; nt++)
            #pragma unroll
            for (int u = 0; u < 4; u++) sa[nt][u] = 0.f;

        #pragma unroll
        for (int kk = 0; kk < 8; kk++) {
            unsigned bf[8][2];
            #pragma unroll
            for (int nt = 0; nt < 8; nt++) {
                bf[nt][0] = __float_as_uint(Ks[(nt * 8 + g) * 68 + kk * 8 + t    ]);
                bf[nt][1] = __float_as_uint(Ks[(nt * 8 + g) * 68 + kk * 8 + t + 4]);
            }
            #pragma unroll
            for (int nt = 0; nt < 8; nt++)
                mma_tf32(sa[nt], qf[kk][0], qf[kk][1], qf[kk][2], qf[kk][3],
                         bf[nt][0], bf[nt][1]);
        }

        const bool mask_tile = causal && (kb >= qb * 2);
        float smax0 = -INFINITY, smax1 = -INFINITY;
        #pragma unroll
        for (int nt = 0; nt < 8; nt++) {
            const int col = kb * 64 + nt * 8 + 2 * t;
            sa[nt][0] *= 0.125f; sa[nt][1] *= 0.125f;
            sa[nt][2] *= 0.125f; sa[nt][3] *= 0.125f;
            if (mask_tile) {
                if (col     > row0)     sa[nt][0] = -1e9f;
                if (col + 1 > row0)     sa[nt][1] = -1e9f;
                if (col     > row0 + 8) sa[nt][2] = -1e9f;
                if (col + 1 > row0 + 8) sa[nt][3] = -1e9f;
            }
            smax0 = fmaxf(smax0, fmaxf(sa[nt][0], sa[nt][1]));
            smax1 = fmaxf(smax1, fmaxf(sa[nt][2], sa[nt][3]));
        }
        smax0 = fmaxf(smax0, __shfl_xor_sync(0xffffffffu, smax0, 1));
        smax0 = fmaxf(smax0, __shfl_xor_sync(0xffffffffu, smax0, 2));
        smax1 = fmaxf(smax1, __shfl_xor_sync(0xffffffffu, smax1, 1));
        smax1 = fmaxf(smax1, __shfl_xor_sync(0xffffffffu, smax1, 2));

        const float m0n = fmaxf(m0, smax0);
        const float m1n = fmaxf(m1, smax1);
        const float cr0 = __expf(m0 - m0n);
        const float cr1 = __expf(m1 - m1n);
        m0 = m0n; m1 = m1n;

        float ls0 = 0.f, ls1 = 0.f;
        #pragma unroll
        for (int nt = 0; nt < 8; nt++) {
            sa[nt][0] = __expf(sa[nt][0] - m0n);
            sa[nt][1] = __expf(sa[nt][1] - m0n);
            sa[nt][2] = __expf(sa[nt][2] - m1n);
            sa[nt][3] = __expf(sa[nt][3] - m1n);
            ls0 += sa[nt][0] + sa[nt][1];
            ls1 += sa[nt][2] + sa[nt][3];
        }
        ls0 += __shfl_xor_sync(0xffffffffu, ls0, 1);
        ls0 += __shfl_xor_sync(0xffffffffu, ls0, 2);
        ls1 += __shfl_xor_sync(0xffffffffu, ls1, 1);
        ls1 += __shfl_xor_sync(0xffffffffu, ls1, 2);
        l0 = l0 * cr0 + ls0;
        l1 = l1 * cr1 + ls1;

        #pragma unroll
        for (int nt = 0; nt < 8; nt++) {
            oacc[nt][0] *= cr0; oacc[nt][1] *= cr0;
            oacc[nt][2] *= cr1; oacc[nt][3] *= cr1;
        }

        const int src0 = (lane & 28) | (t >> 1);
        const int src1 = src0 + 2;
        const bool odd = t & 1;
        #pragma unroll
        for (int j = 0; j < 8; j++) {
            float p0a = __shfl_sync(0xffffffffu, sa[j][0], src0);
            float p1a = __shfl_sync(0xffffffffu, sa[j][1], src0);
            float p0b = __shfl_sync(0xffffffffu, sa[j][0], src1);
            float p1b = __shfl_sync(0xffffffffu, sa[j][1], src1);
            float r0a = __shfl_sync(0xffffffffu, sa[j][2], src0);
            float r1a = __shfl_sync(0xffffffffu, sa[j][3], src0);
            float r0b = __shfl_sync(0xffffffffu, sa[j][2], src1);
            float r1b = __shfl_sync(0xffffffffu, sa[j][3], src1);
            const unsigned a0 = __float_as_uint(f2tf32(odd ? p1a : p0a));
            const unsigned a1 = __float_as_uint(f2tf32(odd ? r1a : r0a));
            const unsigned a2 = __float_as_uint(f2tf32(odd ? p1b : p0b));
            const unsigned a3 = __float_as_uint(f2tf32(odd ? r1b : r0b));
            #pragma unroll
            for (int nt = 0; nt < 8; nt++) {
                const unsigned b0 = __float_as_uint(Vs[(j * 8 + t    ) * 68 + nt * 8 + g]);
                const unsigned b1 = __float_as_uint(Vs[(j * 8 + t + 4) * 68 + nt * 8 + g]);
                mma_tf32(oacc[nt], a0, a1, a2, a3, b0, b1);
            }
        }
    }

    const float inv0 = 1.f / l0;
    const float inv1 = 1.f / l1;
    float* op = O + ((size_t)(b * S_ + row0)) * DM + h * DH;
    #pragma unroll
    for (int nt = 0; nt < 8; nt++) {
        float2 v;
        v.x = oacc[nt][0] * inv0; v.y = oacc[nt][1] * inv0;
        *(float2*)&op[nt * 8 + 2 * t] = v;
        v.x = oacc[nt][2] * inv1; v.y = oacc[nt][3] * inv1;
        *(float2*)&op[(size_t)8 * DM + nt * 8 + 2 * t] = v;
    }
}

// ---------------- residual add + layernorm (one row per CTA) -------------
__global__ __launch_bounds__(256)
void ln_kernel(const float* __restrict__ att, const float* __restrict__ resid,
               const float* __restrict__ g, const float* __restrict__ bt,
               float* __restrict__ xout)
{
    const int row = blockIdx.x;
    const int tid = threadIdx.x;

    float4 a = *(const float4*)&att  [(size_t)row * DM + tid * 4];
    float4 r = *(const float4*)&resid[(size_t)row * DM + tid * 4];
    float4 v;
    v.x = a.x + r.x; v.y = a.y + r.y; v.z = a.z + r.z; v.w = a.w + r.w;

    float s1 = v.x + v.y + v.z + v.w;
    float s2 = v.x*v.x + v.y*v.y + v.z*v.z + v.w*v.w;

    __shared__ float sh1[8], sh2[8];
    #pragma unroll
    for (int o = 16; o > 0; o >>= 1) {
        s1 += __shfl_xor_sync(0xffffffffu, s1, o);
        s2 += __shfl_xor_sync(0xffffffffu, s2, o);
    }
    if ((tid & 31) == 0) { sh1[tid >> 5] = s1; sh2[tid >> 5] = s2; }
    __syncthreads();
    float t1 = 0.f, t2 = 0.f;
    #pragma unroll
    for (int i = 0; i < 8; i++) { t1 += sh1[i]; t2 += sh2[i]; }

    const float mu  = t1 * (1.0f / DM);
    const float var = t2 * (1.0f / DM) - mu * mu;
    const float rs  = rsqrtf(var + 1e-5f);

    float4 gg = *(const float4*)&g [tid * 4];
    float4 bb = *(const float4*)&bt[tid * 4];
    float4 o;
    o.x = (v.x - mu) * rs * gg.x + bb.x;
    o.y = (v.y - mu) * rs * gg.y + bb.y;
    o.z = (v.z - mu) * rs * gg.z + bb.z;
    o.w = (v.w - mu) * rs * gg.w + bb.w;
    *(float4*)&xout[(size_t)row * DM + tid * 4] = o;
}

// ---------------- launch ---------------------------------------------------
extern "C" void kernel_launch(void* const* d_in, const int* in_sizes, int n_in,
                              void* d_out, int out_size)
{
    const float* q    = (const float*)d_in[0];
    const float* k    = (const float*)d_in[1];
    const float* Wq   = (const float*)d_in[2];
    const float* bq   = (const float*)d_in[3];
    const float* Wk   = (const float*)d_in[4];
    const float* bk   = (const float*)d_in[5];
    const float* Wv   = (const float*)d_in[6];
    const float* bv   = (const float*)d_in[7];
    const float* W1   = (const float*)d_in[8];
    const float* b1   = (const float*)d_in[9];
    const float* W2   = (const float*)d_in[10];
    const float* b2   = (const float*)d_in[11];
    const float* ln_g = (const float*)d_in[12];
    const float* ln_b = (const float*)d_in[13];
    const int*   msk  = (const int*)d_in[14];

    float *Qb, *Kb, *Vb, *Ab, *Xb, *Hb;
    cudaGetSymbolAddress((void**)&Qb, g_Q);
    cudaGetSymbolAddress((void**)&Kb, g_K);
    cudaGetSymbolAddress((void**)&Vb, g_V);
    cudaGetSymbolAddress((void**)&Ab, g_att);
    cudaGetSymbolAddress((void**)&Xb, g_x);
    cudaGetSymbolAddress((void**)&Hb, g_h);

    // QKV projections: [4096,1024] @ [1024,1024]^T
    gemm_h<0><<<dim3(DM / 128, MTOK / 128), 256>>>(q, Wq, bq, Qb, nullptr, MTOK, DM, DM);
    gemm_h<0><<<dim3(DM / 128, MTOK / 128), 256>>>(k, Wk, bk, Kb, nullptr, MTOK, DM, DM);
    gemm_h<0><<<dim3(DM / 128, MTOK / 128), 256>>>(k, Wv, bv, Vb, nullptr, MTOK, DM, DM);

    // causal attention (tensor cores)
    attn_tc<<<dim3(S_ / 128, H_, B_), 256>>>(Qb, Kb, Vb, Ab, msk);

    // residual + layernorm
    ln_kernel<<<MTOK, 256>>>(Ab, q, ln_g, ln_b, Xb);

    // FFN: gelu(x @ W1^T + b1) @ W2^T + b2 + x
    gemm_h<1><<<dim3(DFF / 128, MTOK / 128), 256>>>(Xb, W1, b1, Hb, nullptr, MTOK, DFF, DM);
    gemm_h<2><<<dim3(DM / 128, MTOK / 128), 256>>>(Hb, W2, b2, (float*)d_out, Xb, MTOK, DM, DFF);
}

// round 8
// speedup vs baseline: 3.3291x; 1.1372x over previous
#include <cuda_runtime.h>
#include <cuda_fp16.h>
#include <math.h>
#include <stdint.h>

#define B_    2
#define S_    2048
#define DM    1024
#define H_    16
#define DH    64
#define DFF   4096
#define MTOK  (B_*S_)      // 4096 token rows

// ---------------- scratch (device globals; no allocation) ----------------
__device__ float g_Q[MTOK*DM];
__device__ float g_K[MTOK*DM];
__device__ float g_V[MTOK*DM];
__device__ float g_att[MTOK*DM];
__device__ float g_x[MTOK*DM];
__device__ float g_h[(size_t)MTOK*DFF];

// ---------------- helpers -------------------------------------------------
__device__ __forceinline__ void mma_f16(float c[4],
                                        unsigned a0, unsigned a1, unsigned a2, unsigned a3,
                                        unsigned b0, unsigned b1) {
    asm volatile("mma.sync.aligned.m16n8k16.row.col.f32.f16.f16.f32 "
                 "{%0,%1,%2,%3}, {%4,%5,%6,%7}, {%8,%9}, {%0,%1,%2,%3};"
                 : "+f"(c[0]), "+f"(c[1]), "+f"(c[2]), "+f"(c[3])
                 : "r"(a0), "r"(a1), "r"(a2), "r"(a3), "r"(b0), "r"(b1));
}

#define LDSM_X4(r0, r1, r2, r3, addr) \
    asm volatile("ldmatrix.sync.aligned.m8n8.x4.shared.b16 {%0,%1,%2,%3}, [%4];" \
                 : "=r"(r0), "=r"(r1), "=r"(r2), "=r"(r3) : "r"(addr))

#define LDSM_X4T(r0, r1, r2, r3, addr) \
    asm volatile("ldmatrix.sync.aligned.m8n8.x4.trans.shared.b16 {%0,%1,%2,%3}, [%4];" \
                 : "=r"(r0), "=r"(r1), "=r"(r2), "=r"(r3) : "r"(addr))

// pack two floats -> f16x2 register (lo = a, hi = b)
__device__ __forceinline__ unsigned packh2(float a, float b) {
    unsigned r;
    asm("cvt.rn.f16x2.f32 %0, %1, %2;" : "=r"(r) : "f"(b), "f"(a));
    return r;
}

// ---------------- fp16 tensor-core GEMM, NT (R6, known-good) --------------
#define KCH 32
#define HP  40            // half pitch: 80 bytes = 5*16 -> conflict-free ldmatrix

template<int EPI>
__global__ __launch_bounds__(256)
void gemm_h(const float* __restrict__ A, const float* __restrict__ Bm,
            const float* __restrict__ bias, float* __restrict__ C,
            const float* __restrict__ res, int M, int N, int K)
{
    __shared__ __half As[2][128 * HP];
    __shared__ __half Bs[2][128 * HP];

    const int tid  = threadIdx.x;
    const int m0   = blockIdx.y * 128;
    const int n0   = blockIdx.x * 128;
    const int lane = tid & 31;
    const int w    = tid >> 5;
    const int wm   = (w >> 2) * 64;
    const int wn   = (w & 3) * 32;
    const int g    = lane >> 2;
    const int t    = lane & 3;

    float acc[4][4][4];
    #pragma unroll
    for (int i = 0; i < 4; i++)
        #pragma unroll
        for (int j = 0; j < 4; j++)
            #pragma unroll
            for (int u = 0; u < 4; u++) acc[i][j][u] = 0.f;

    const uint32_t sA = (uint32_t)__cvta_generic_to_shared(&As[0][0]);
    const uint32_t sB = (uint32_t)__cvta_generic_to_shared(&Bs[0][0]);
    const uint32_t BUFO = 128 * HP * 2;

    const uint32_t a_base = sA + (((uint32_t)(wm + (lane & 15))) * HP + ((lane >> 4) * 8)) * 2;
    const uint32_t b_base = sB + (((uint32_t)(wn + (lane & 7)))  * HP + ((lane >> 3) * 8)) * 2;

    float4 ra[4], rb[4];
    const int srow = tid >> 3;
    const int sg4  = tid & 7;

    auto gload = [&](int k0) {
        #pragma unroll
        for (int i = 0; i < 4; i++) {
            const int row = srow + i * 32;
            ra[i] = *(const float4*)&A [(size_t)(m0 + row) * K + k0 + sg4 * 4];
            rb[i] = *(const float4*)&Bm[(size_t)(n0 + row) * K + k0 + sg4 * 4];
        }
    };
    auto sts = [&](int buf) {
        #pragma unroll
        for (int i = 0; i < 4; i++) {
            const int row = srow + i * 32;
            const int idx = row * HP + sg4 * 4;
            __half2 h0 = __floats2half2_rn(ra[i].x, ra[i].y);
            __half2 h1 = __floats2half2_rn(ra[i].z, ra[i].w);
            *(__half2*)&As[buf][idx]     = h0;
            *(__half2*)&As[buf][idx + 2] = h1;
            h0 = __floats2half2_rn(rb[i].x, rb[i].y);
            h1 = __floats2half2_rn(rb[i].z, rb[i].w);
            *(__half2*)&Bs[buf][idx]     = h0;
            *(__half2*)&Bs[buf][idx + 2] = h1;
        }
    };
    auto compute = [&](int buf) {
        const uint32_t bo = buf ? BUFO : 0;
        unsigned bq[4][4];
        #pragma unroll
        for (int nt = 0; nt < 4; nt++)
            LDSM_X4(bq[nt][0], bq[nt][1], bq[nt][2], bq[nt][3],
                    b_base + bo + nt * (8 * HP * 2));
        #pragma unroll
        for (int kh = 0; kh < 2; kh++) {
            unsigned aq[4][4];
            #pragma unroll
            for (int mt = 0; mt < 4; mt++)
                LDSM_X4(aq[mt][0], aq[mt][1], aq[mt][2], aq[mt][3],
                        a_base + bo + mt * (16 * HP * 2) + kh * 32);
            #pragma unroll
            for (int mt = 0; mt < 4; mt++)
                #pragma unroll
                for (int nt = 0; nt < 4; nt++)
                    mma_f16(acc[mt][nt], aq[mt][0], aq[mt][1], aq[mt][2], aq[mt][3],
                            bq[nt][kh * 2], bq[nt][kh * 2 + 1]);
        }
    };

    const int NC = K / KCH;
    gload(0);
    sts(0);
    __syncthreads();
    for (int c = 0; c < NC; c++) {
        if (c + 1 < NC) gload((c + 1) * KCH);
        compute(c & 1);
        if (c + 1 < NC) sts((c + 1) & 1);
        __syncthreads();
    }

    #pragma unroll
    for (int mt = 0; mt < 4; mt++) {
        #pragma unroll
        for (int half = 0; half < 2; half++) {
            const int row = m0 + wm + mt * 16 + g + half * 8;
            #pragma unroll
            for (int nt = 0; nt < 4; nt++) {
                const int col = n0 + wn + nt * 8 + 2 * t;
                float v0 = acc[mt][nt][half * 2 + 0] + bias[col];
                float v1 = acc[mt][nt][half * 2 + 1] + bias[col + 1];
                if (EPI == 1) {
                    v0 = 0.5f * v0 * (1.0f + erff(v0 * 0.70710678118654752f));
                    v1 = 0.5f * v1 * (1.0f + erff(v1 * 0.70710678118654752f));
                } else if (EPI == 2) {
                    v0 += res[(size_t)row * N + col];
                    v1 += res[(size_t)row * N + col + 1];
                }
                float2 o; o.x = v0; o.y = v1;
                *(float2*)&C[(size_t)row * N + col] = o;
            }
        }
    }
}

// ---------------- fp16 tensor-core causal flash attention ----------------
// CTA: 128 q rows, 8 warps (16 rows each). kv tiles of 64. fp16 smem [key][dim].
#define AP 72   // half pitch: 144B = 9*16 -> conflict-free ldmatrix rows

__global__ __launch_bounds__(256)
void attn_tc(const float* __restrict__ Q, const float* __restrict__ K,
             const float* __restrict__ V, float* __restrict__ O,
             const int* __restrict__ use_mask)
{
    __shared__ __half Ks[64 * AP];
    __shared__ __half Vs[64 * AP];

    const int tid  = threadIdx.x;
    const int lane = tid & 31;
    const int w    = tid >> 5;
    const int g    = lane >> 2;
    const int t    = lane & 3;
    const int qb   = (gridDim.x - 1) - blockIdx.x;   // heavy q-blocks first
    const int h    = blockIdx.y;
    const int b    = blockIdx.z;
    const int q0   = qb * 128;
    const int causal = use_mask[0];
    const int row0 = q0 + w * 16 + g;                // rows row0, row0+8

    // Q fragments (fp16 A-layout, m16n8k16), resident whole kernel
    unsigned qf[4][4];
    {
        const float* qp  = Q + ((size_t)(b * S_ + row0)) * DM + h * DH;
        const float* qp8 = qp + 8 * DM;
        #pragma unroll
        for (int ks = 0; ks < 4; ks++) {
            const int c = ks * 16 + 2 * t;
            qf[ks][0] = packh2(qp [c],     qp [c + 1]);
            qf[ks][1] = packh2(qp8[c],     qp8[c + 1]);
            qf[ks][2] = packh2(qp [c + 8], qp [c + 9]);
            qf[ks][3] = packh2(qp8[c + 8], qp8[c + 9]);
        }
    }

    const uint32_t sK = (uint32_t)__cvta_generic_to_shared(&Ks[0]);
    const uint32_t sV = (uint32_t)__cvta_generic_to_shared(&Vs[0]);
    // K ldmatrix (non-trans): row = key, col-group selector = lane>>3
    const uint32_t k_base = sK + (((uint32_t)(lane & 7)) * AP + ((lane >> 3) * 8)) * 2;
    // V ldmatrix (trans): row = key (lane&15), dim-group selector = lane>>4
    const uint32_t v_base = sV + (((uint32_t)(lane & 15)) * AP + ((lane >> 4) * 8)) * 2;

    float m0 = -INFINITY, m1 = -INFINITY, l0 = 0.f, l1 = 0.f;
    float oacc[8][4];
    #pragma unroll
    for (int nt = 0; nt < 8; nt++)
        #pragma unroll
        for (int u = 0; u < 4; u++) oacc[nt][u] = 0.f;

    const int nkb = causal ? (qb * 2 + 2) : (S_ / 64);

    // staging: slot s = tid + i*256 -> row = s>>4, col4 = (s&15)*4
    const int sr = tid >> 4;
    const int sc = (tid & 15) * 4;
    float4 pk[4], pv[4];
    #pragma unroll
    for (int i = 0; i < 4; i++) {
        size_t src = ((size_t)(b * S_ + sr + i * 16)) * DM + h * DH + sc;
        pk[i] = *(const float4*)&K[src];
        pv[i] = *(const float4*)&V[src];
    }

    for (int kb = 0; kb < nkb; kb++) {
        __syncthreads();   // prior tile fully consumed
        #pragma unroll
        for (int i = 0; i < 4; i++) {
            const int idx = (sr + i * 16) * AP + sc;
            *(__half2*)&Ks[idx]     = __floats2half2_rn(pk[i].x, pk[i].y);
            *(__half2*)&Ks[idx + 2] = __floats2half2_rn(pk[i].z, pk[i].w);
            *(__half2*)&Vs[idx]     = __floats2half2_rn(pv[i].x, pv[i].y);
            *(__half2*)&Vs[idx + 2] = __floats2half2_rn(pv[i].z, pv[i].w);
        }
        __syncthreads();

        // prefetch next tile
        if (kb + 1 < nkb) {
            #pragma unroll
            for (int i = 0; i < 4; i++) {
                size_t src = ((size_t)(b * S_ + (kb + 1) * 64 + sr + i * 16)) * DM + h * DH + sc;
                pk[i] = *(const float4*)&K[src];
                pv[i] = *(const float4*)&V[src];
            }
        }

        // ---- S = Q K^T (16x64 per warp) ----
        float sa[8][4];
        #pragma unroll
        for (int nt = 0; nt < 8; nt++)
            #pragma unroll
            for (int u = 0; u < 4; u++) sa[nt][u] = 0.f;

        #pragma unroll
        for (int nt = 0; nt < 8; nt++) {
            unsigned kq[8];
            LDSM_X4(kq[0], kq[1], kq[2], kq[3], k_base + (nt * 8 * AP) * 2);
            LDSM_X4(kq[4], kq[5], kq[6], kq[7], k_base + (nt * 8 * AP) * 2 + 64);
            #pragma unroll
            for (int ks = 0; ks < 4; ks++)
                mma_f16(sa[nt], qf[ks][0], qf[ks][1], qf[ks][2], qf[ks][3],
                        kq[ks * 2], kq[ks * 2 + 1]);
        }

        // ---- softmax (registers) ----
        const bool mask_tile = causal && (kb >= qb * 2);
        float smax0 = -INFINITY, smax1 = -INFINITY;
        #pragma unroll
        for (int nt = 0; nt < 8; nt++) {
            const int col = kb * 64 + nt * 8 + 2 * t;
            sa[nt][0] *= 0.125f; sa[nt][1] *= 0.125f;
            sa[nt][2] *= 0.125f; sa[nt][3] *= 0.125f;
            if (mask_tile) {
                if (col     > row0)     sa[nt][0] = -1e9f;
                if (col + 1 > row0)     sa[nt][1] = -1e9f;
                if (col     > row0 + 8) sa[nt][2] = -1e9f;
                if (col + 1 > row0 + 8) sa[nt][3] = -1e9f;
            }
            smax0 = fmaxf(smax0, fmaxf(sa[nt][0], sa[nt][1]));
            smax1 = fmaxf(smax1, fmaxf(sa[nt][2], sa[nt][3]));
        }
        smax0 = fmaxf(smax0, __shfl_xor_sync(0xffffffffu, smax0, 1));
        smax0 = fmaxf(smax0, __shfl_xor_sync(0xffffffffu, smax0, 2));
        smax1 = fmaxf(smax1, __shfl_xor_sync(0xffffffffu, smax1, 1));
        smax1 = fmaxf(smax1, __shfl_xor_sync(0xffffffffu, smax1, 2));

        const float m0n = fmaxf(m0, smax0);
        const float m1n = fmaxf(m1, smax1);
        const float cr0 = __expf(m0 - m0n);
        const float cr1 = __expf(m1 - m1n);
        m0 = m0n; m1 = m1n;

        float ls0 = 0.f, ls1 = 0.f;
        #pragma unroll
        for (int nt = 0; nt < 8; nt++) {
            sa[nt][0] = __expf(sa[nt][0] - m0n);
            sa[nt][1] = __expf(sa[nt][1] - m0n);
            sa[nt][2] = __expf(sa[nt][2] - m1n);
            sa[nt][3] = __expf(sa[nt][3] - m1n);
            ls0 += sa[nt][0] + sa[nt][1];
            ls1 += sa[nt][2] + sa[nt][3];
        }
        ls0 += __shfl_xor_sync(0xffffffffu, ls0, 1);
        ls0 += __shfl_xor_sync(0xffffffffu, ls0, 2);
        ls1 += __shfl_xor_sync(0xffffffffu, ls1, 1);
        ls1 += __shfl_xor_sync(0xffffffffu, ls1, 2);
        l0 = l0 * cr0 + ls0;
        l1 = l1 * cr1 + ls1;

        #pragma unroll
        for (int nt = 0; nt < 8; nt++) {
            oacc[nt][0] *= cr0; oacc[nt][1] *= cr0;
            oacc[nt][2] *= cr1; oacc[nt][3] *= cr1;
        }

        // ---- O += P V : P packs directly into A-fragments (no shuffles) ----
        #pragma unroll
        for (int ks = 0; ks < 4; ks++) {
            const unsigned a0 = packh2(sa[2*ks  ][0], sa[2*ks  ][1]);
            const unsigned a1 = packh2(sa[2*ks  ][2], sa[2*ks  ][3]);
            const unsigned a2 = packh2(sa[2*ks+1][0], sa[2*ks+1][1]);
            const unsigned a3 = packh2(sa[2*ks+1][2], sa[2*ks+1][3]);
            #pragma unroll
            for (int dg = 0; dg < 4; dg++) {
                unsigned v0, v1, v2, v3;
                LDSM_X4T(v0, v1, v2, v3, v_base + (ks * 16 * AP + dg * 16) * 2);
                mma_f16(oacc[2*dg    ], a0, a1, a2, a3, v0, v1);
                mma_f16(oacc[2*dg + 1], a0, a1, a2, a3, v2, v3);
            }
        }
    }

    const float inv0 = 1.f / l0;
    const float inv1 = 1.f / l1;
    float* op = O + ((size_t)(b * S_ + row0)) * DM + h * DH;
    #pragma unroll
    for (int nt = 0; nt < 8; nt++) {
        float2 v;
        v.x = oacc[nt][0] * inv0; v.y = oacc[nt][1] * inv0;
        *(float2*)&op[nt * 8 + 2 * t] = v;
        v.x = oacc[nt][2] * inv1; v.y = oacc[nt][3] * inv1;
        *(float2*)&op[(size_t)8 * DM + nt * 8 + 2 * t] = v;
    }
}

// ---------------- residual add + layernorm (one row per CTA) -------------
__global__ __launch_bounds__(256)
void ln_kernel(const float* __restrict__ att, const float* __restrict__ resid,
               const float* __restrict__ g, const float* __restrict__ bt,
               float* __restrict__ xout)
{
    const int row = blockIdx.x;
    const int tid = threadIdx.x;

    float4 a = *(const float4*)&att  [(size_t)row * DM + tid * 4];
    float4 r = *(const float4*)&resid[(size_t)row * DM + tid * 4];
    float4 v;
    v.x = a.x + r.x; v.y = a.y + r.y; v.z = a.z + r.z; v.w = a.w + r.w;

    float s1 = v.x + v.y + v.z + v.w;
    float s2 = v.x*v.x + v.y*v.y + v.z*v.z + v.w*v.w;

    __shared__ float sh1[8], sh2[8];
    #pragma unroll
    for (int o = 16; o > 0; o >>= 1) {
        s1 += __shfl_xor_sync(0xffffffffu, s1, o);
        s2 += __shfl_xor_sync(0xffffffffu, s2, o);
    }
    if ((tid & 31) == 0) { sh1[tid >> 5] = s1; sh2[tid >> 5] = s2; }
    __syncthreads();
    float t1 = 0.f, t2 = 0.f;
    #pragma unroll
    for (int i = 0; i < 8; i++) { t1 += sh1[i]; t2 += sh2[i]; }

    const float mu  = t1 * (1.0f / DM);
    const float var = t2 * (1.0f / DM) - mu * mu;
    const float rs  = rsqrtf(var + 1e-5f);

    float4 gg = *(const float4*)&g [tid * 4];
    float4 bb = *(const float4*)&bt[tid * 4];
    float4 o;
    o.x = (v.x - mu) * rs * gg.x + bb.x;
    o.y = (v.y - mu) * rs * gg.y + bb.y;
    o.z = (v.z - mu) * rs * gg.z + bb.z;
    o.w = (v.w - mu) * rs * gg.w + bb.w;
    *(float4*)&xout[(size_t)row * DM + tid * 4] = o;
}

// ---------------- launch ---------------------------------------------------
extern "C" void kernel_launch(void* const* d_in, const int* in_sizes, int n_in,
                              void* d_out, int out_size)
{
    const float* q    = (const float*)d_in[0];
    const float* k    = (const float*)d_in[1];
    const float* Wq   = (const float*)d_in[2];
    const float* bq   = (const float*)d_in[3];
    const float* Wk   = (const float*)d_in[4];
    const float* bk   = (const float*)d_in[5];
    const float* Wv   = (const float*)d_in[6];
    const float* bv   = (const float*)d_in[7];
    const float* W1   = (const float*)d_in[8];
    const float* b1   = (const float*)d_in[9];
    const float* W2   = (const float*)d_in[10];
    const float* b2   = (const float*)d_in[11];
    const float* ln_g = (const float*)d_in[12];
    const float* ln_b = (const float*)d_in[13];
    const int*   msk  = (const int*)d_in[14];

    float *Qb, *Kb, *Vb, *Ab, *Xb, *Hb;
    cudaGetSymbolAddress((void**)&Qb, g_Q);
    cudaGetSymbolAddress((void**)&Kb, g_K);
    cudaGetSymbolAddress((void**)&Vb, g_V);
    cudaGetSymbolAddress((void**)&Ab, g_att);
    cudaGetSymbolAddress((void**)&Xb, g_x);
    cudaGetSymbolAddress((void**)&Hb, g_h);

    // QKV projections: [4096,1024] @ [1024,1024]^T
    gemm_h<0><<<dim3(DM / 128, MTOK / 128), 256>>>(q, Wq, bq, Qb, nullptr, MTOK, DM, DM);
    gemm_h<0><<<dim3(DM / 128, MTOK / 128), 256>>>(k, Wk, bk, Kb, nullptr, MTOK, DM, DM);
    gemm_h<0><<<dim3(DM / 128, MTOK / 128), 256>>>(k, Wv, bv, Vb, nullptr, MTOK, DM, DM);

    // causal attention (fp16 tensor cores)
    attn_tc<<<dim3(S_ / 128, H_, B_), 256>>>(Qb, Kb, Vb, Ab, msk);

    // residual + layernorm
    ln_kernel<<<MTOK, 256>>>(Ab, q, ln_g, ln_b, Xb);

    // FFN: gelu(x @ W1^T + b1) @ W2^T + b2 + x
    gemm_h<1><<<dim3(DFF / 128, MTOK / 128), 256>>>(Xb, W1, b1, Hb, nullptr, MTOK, DFF, DM);
    gemm_h<2><<<dim3(DM / 128, MTOK / 128), 256>>>(Hb, W2, b2, (float*)d_out, Xb, MTOK, DM, DFF);
}

// round 9
// speedup vs baseline: 4.7540x; 1.4280x over previous
#include <cuda_runtime.h>
#include <cuda_fp16.h>
#include <math.h>
#include <stdint.h>

#define B_    2
#define S_    2048
#define DM    1024
#define H_    16
#define DH    64
#define DFF   4096
#define MTOK  (B_*S_)      // 4096 token rows

// ---------------- scratch (device globals; no allocation) ----------------
__device__ __half g_q16 [MTOK*DM];
__device__ __half g_k16 [MTOK*DM];
__device__ __half g_wq16[DM*DM];
__device__ __half g_wk16[DM*DM];
__device__ __half g_wv16[DM*DM];
__device__ __half g_w116[(size_t)DFF*DM];
__device__ __half g_w216[(size_t)DM*DFF];
__device__ __half g_Qh  [MTOK*DM];
__device__ __half g_Kh  [MTOK*DM];
__device__ __half g_Vh  [MTOK*DM];
__device__ __half g_Xh  [MTOK*DM];
__device__ __half g_Hh  [(size_t)MTOK*DFF];
__device__ float  g_att [MTOK*DM];
__device__ float  g_x   [MTOK*DM];

// ---------------- helpers -------------------------------------------------
__device__ __forceinline__ void mma_f16(float c[4],
                                        unsigned a0, unsigned a1, unsigned a2, unsigned a3,
                                        unsigned b0, unsigned b1) {
    asm volatile("mma.sync.aligned.m16n8k16.row.col.f32.f16.f16.f32 "
                 "{%0,%1,%2,%3}, {%4,%5,%6,%7}, {%8,%9}, {%0,%1,%2,%3};"
                 : "+f"(c[0]), "+f"(c[1]), "+f"(c[2]), "+f"(c[3])
                 : "r"(a0), "r"(a1), "r"(a2), "r"(a3), "r"(b0), "r"(b1));
}

#define LDSM_X4(r0, r1, r2, r3, addr) \
    asm volatile("ldmatrix.sync.aligned.m8n8.x4.shared.b16 {%0,%1,%2,%3}, [%4];" \
                 : "=r"(r0), "=r"(r1), "=r"(r2), "=r"(r3) : "r"(addr))

#define LDSM_X4T(r0, r1, r2, r3, addr) \
    asm volatile("ldmatrix.sync.aligned.m8n8.x4.trans.shared.b16 {%0,%1,%2,%3}, [%4];" \
                 : "=r"(r0), "=r"(r1), "=r"(r2), "=r"(r3) : "r"(addr))

// pack two floats -> f16x2 register (lo = a, hi = b)
__device__ __forceinline__ unsigned packh2(float a, float b) {
    unsigned r;
    asm("cvt.rn.f16x2.f32 %0, %1, %2;" : "=r"(r) : "f"(b), "f"(a));
    return r;
}

// ---------------- fp32 -> fp16 conversion pass ----------------------------
__global__ __launch_bounds__(256)
void f2h(const float4* __restrict__ src, uint2* __restrict__ dst, int n4)
{
    const int i = blockIdx.x * 256 + threadIdx.x;
    if (i < n4) {
        float4 v = src[i];
        uint2 o;
        o.x = packh2(v.x, v.y);
        o.y = packh2(v.z, v.w);
        dst[i] = o;
    }
}

// ---------------- fp16-operand tensor-core GEMM, NT -----------------------
// C[m,n] = sum_k A[m,k]*B[n,k]. Tile 128x128, KC=64, double-buffered.
// 8 warps 2(m) x 4(n), warp tile 64x32.
// EPI: 0 = +bias -> fp16 out; 1 = gelu(+bias) -> fp16 out; 2 = +bias+res -> fp32 out
#define KC64 64
#define HPG  72                      // pitch 72 halves = 144B = 9*16
#define GBUF (128 * HPG * 2)         // bytes per buffer per operand
#define GSMEM (4 * GBUF)             // 73728 bytes dynamic smem

template<int EPI>
__global__ __launch_bounds__(256)
void gemm16(const __half* __restrict__ A, const __half* __restrict__ Bm,
            const float* __restrict__ bias, void* __restrict__ Cout,
            const float* __restrict__ res, int M, int N, int K)
{
    extern __shared__ char smem[];
    __half* As = (__half*)smem;                     // [2][128*HPG]
    __half* Bs = (__half*)(smem + 2 * GBUF);

    const int tid  = threadIdx.x;
    const int m0   = blockIdx.y * 128;
    const int n0   = blockIdx.x * 128;
    const int lane = tid & 31;
    const int w    = tid >> 5;
    const int wm   = (w >> 2) * 64;
    const int wn   = (w & 3) * 32;
    const int g    = lane >> 2;
    const int t    = lane & 3;

    float acc[4][4][4];
    #pragma unroll
    for (int i = 0; i < 4; i++)
        #pragma unroll
        for (int j = 0; j < 4; j++)
            #pragma unroll
            for (int u = 0; u < 4; u++) acc[i][j][u] = 0.f;

    const uint32_t sA = (uint32_t)__cvta_generic_to_shared(As);
    const uint32_t sB = (uint32_t)__cvta_generic_to_shared(Bs);
    const uint32_t a_base = sA + (((uint32_t)(wm + (lane & 15))) * HPG + ((lane >> 4) * 8)) * 2;
    const uint32_t b_base = sB + (((uint32_t)(wn + (lane & 7)))  * HPG + ((lane >> 3) * 8)) * 2;

    // staging: slot s = tid + i*256 (i<4) -> row = s>>3 (0..127), grp = s&7 (8 halves)
    uint4 ra[4], rb[4];
    const int srow = tid >> 3;
    const int sgrp = tid & 7;

    auto gload = [&](int k0) {
        #pragma unroll
        for (int i = 0; i < 4; i++) {
            const int row = srow + i * 32;
            ra[i] = *(const uint4*)&A [(size_t)(m0 + row) * K + k0 + sgrp * 8];
            rb[i] = *(const uint4*)&Bm[(size_t)(n0 + row) * K + k0 + sgrp * 8];
        }
    };
    auto sts = [&](int buf) {
        __half* pa = As + buf * (128 * HPG);
        __half* pb = Bs + buf * (128 * HPG);
        #pragma unroll
        for (int i = 0; i < 4; i++) {
            const int idx = (srow + i * 32) * HPG + sgrp * 8;
            *(uint4*)&pa[idx] = ra[i];
            *(uint4*)&pb[idx] = rb[i];
        }
    };
    auto compute = [&](int buf) {
        const uint32_t bo = (uint32_t)buf * GBUF;
        unsigned bq[4][8];
        #pragma unroll
        for (int nt = 0; nt < 4; nt++) {
            LDSM_X4(bq[nt][0], bq[nt][1], bq[nt][2], bq[nt][3],
                    b_base + bo + nt * (8 * HPG * 2));
            LDSM_X4(bq[nt][4], bq[nt][5], bq[nt][6], bq[nt][7],
                    b_base + bo + nt * (8 * HPG * 2) + 64);
        }
        #pragma unroll
        for (int kh = 0; kh < 4; kh++) {
            unsigned aq[4][4];
            #pragma unroll
            for (int mt = 0; mt < 4; mt++)
                LDSM_X4(aq[mt][0], aq[mt][1], aq[mt][2], aq[mt][3],
                        a_base + bo + mt * (16 * HPG * 2) + kh * 32);
            #pragma unroll
            for (int mt = 0; mt < 4; mt++)
                #pragma unroll
                for (int nt = 0; nt < 4; nt++)
                    mma_f16(acc[mt][nt], aq[mt][0], aq[mt][1], aq[mt][2], aq[mt][3],
                            bq[nt][kh * 2], bq[nt][kh * 2 + 1]);
        }
    };

    const int NC = K / KC64;
    gload(0);
    sts(0);
    __syncthreads();
    for (int c = 0; c < NC; c++) {
        if (c + 1 < NC) gload((c + 1) * KC64);
        compute(c & 1);
        if (c + 1 < NC) sts((c + 1) & 1);
        __syncthreads();
    }

    // epilogue
    #pragma unroll
    for (int mt = 0; mt < 4; mt++) {
        #pragma unroll
        for (int half = 0; half < 2; half++) {
            const int row = m0 + wm + mt * 16 + g + half * 8;
            #pragma unroll
            for (int nt = 0; nt < 4; nt++) {
                const int col = n0 + wn + nt * 8 + 2 * t;
                float v0 = acc[mt][nt][half * 2 + 0] + bias[col];
                float v1 = acc[mt][nt][half * 2 + 1] + bias[col + 1];
                if (EPI == 1) {
                    v0 = 0.5f * v0 * (1.0f + erff(v0 * 0.70710678118654752f));
                    v1 = 0.5f * v1 * (1.0f + erff(v1 * 0.70710678118654752f));
                }
                if (EPI == 2) {
                    v0 += res[(size_t)row * N + col];
                    v1 += res[(size_t)row * N + col + 1];
                    float2 o; o.x = v0; o.y = v1;
                    *(float2*)&((float*)Cout)[(size_t)row * N + col] = o;
                } else {
                    *(unsigned*)&((__half*)Cout)[(size_t)row * N + col] = packh2(v0, v1);
                }
            }
        }
    }
}

// ---------------- fp16 tensor-core causal flash attention ----------------
// CTA: 128 q rows, 8 warps (16 rows each). kv tiles of 64. fp16 Q/K/V in gmem.
#define AP 72

__global__ __launch_bounds__(256)
void attn_tc(const __half* __restrict__ Q, const __half* __restrict__ K,
             const __half* __restrict__ V, float* __restrict__ O,
             const int* __restrict__ use_mask)
{
    __shared__ __half Ks[64 * AP];
    __shared__ __half Vs[64 * AP];

    const int tid  = threadIdx.x;
    const int lane = tid & 31;
    const int w    = tid >> 5;
    const int g    = lane >> 2;
    const int t    = lane & 3;
    const int qb   = (gridDim.x - 1) - blockIdx.x;   // heavy q-blocks first
    const int h    = blockIdx.y;
    const int b    = blockIdx.z;
    const int q0   = qb * 128;
    const int causal = use_mask[0];
    const int row0 = q0 + w * 16 + g;                // rows row0, row0+8

    // Q fragments: direct fp16 loads (pairs are contiguous)
    unsigned qf[4][4];
    {
        const __half* qp  = Q + ((size_t)(b * S_ + row0)) * DM + h * DH;
        const __half* qp8 = qp + 8 * DM;
        #pragma unroll
        for (int ks = 0; ks < 4; ks++) {
            const int c = ks * 16 + 2 * t;
            qf[ks][0] = *(const unsigned*)&qp [c];
            qf[ks][1] = *(const unsigned*)&qp8[c];
            qf[ks][2] = *(const unsigned*)&qp [c + 8];
            qf[ks][3] = *(const unsigned*)&qp8[c + 8];
        }
    }

    const uint32_t sK = (uint32_t)__cvta_generic_to_shared(&Ks[0]);
    const uint32_t sV = (uint32_t)__cvta_generic_to_shared(&Vs[0]);
    const uint32_t k_base = sK + (((uint32_t)(lane & 7)) * AP + ((lane >> 3) * 8)) * 2;
    const uint32_t v_base = sV + (((uint32_t)(lane & 15)) * AP + ((lane >> 4) * 8)) * 2;

    float m0 = -INFINITY, m1 = -INFINITY, l0 = 0.f, l1 = 0.f;
    float oacc[8][4];
    #pragma unroll
    for (int nt = 0; nt < 8; nt++)
        #pragma unroll
        for (int u = 0; u < 4; u++) oacc[nt][u] = 0.f;

    const int nkb = causal ? (qb * 2 + 2) : (S_ / 64);

    // staging: slot s = tid + i*256 (i<2) -> row = s>>3 (0..63), grp = s&7 (8 halves)
    const int sr = tid >> 3;
    const int sg = tid & 7;
    uint4 pk[2], pv[2];
    #pragma unroll
    for (int i = 0; i < 2; i++) {
        size_t src = ((size_t)(b * S_ + sr + i * 32)) * DM + h * DH + sg * 8;
        pk[i] = *(const uint4*)&K[src];
        pv[i] = *(const uint4*)&V[src];
    }

    for (int kb = 0; kb < nkb; kb++) {
        __syncthreads();   // prior tile fully consumed
        #pragma unroll
        for (int i = 0; i < 2; i++) {
            const int idx = (sr + i * 32) * AP + sg * 8;
            *(uint4*)&Ks[idx] = pk[i];
            *(uint4*)&Vs[idx] = pv[i];
        }
        __syncthreads();

        // prefetch next tile
        if (kb + 1 < nkb) {
            #pragma unroll
            for (int i = 0; i < 2; i++) {
                size_t src = ((size_t)(b * S_ + (kb + 1) * 64 + sr + i * 32)) * DM + h * DH + sg * 8;
                pk[i] = *(const uint4*)&K[src];
                pv[i] = *(const uint4*)&V[src];
            }
        }

        // ---- S = Q K^T (16x64 per warp) ----
        float sa[8][4];
        #pragma unroll
        for (int nt = 0; nt < 8; nt++)
            #pragma unroll
            for (int u = 0; u < 4; u++) sa[nt][u] = 0.f;

        #pragma unroll
        for (int nt = 0; nt < 8; nt++) {
            unsigned kq[8];
            LDSM_X4(kq[0], kq[1], kq[2], kq[3], k_base + (nt * 8 * AP) * 2);
            LDSM_X4(kq[4], kq[5], kq[6], kq[7], k_base + (nt * 8 * AP) * 2 + 64);
            #pragma unroll
            for (int ks = 0; ks < 4; ks++)
                mma_f16(sa[nt], qf[ks][0], qf[ks][1], qf[ks][2], qf[ks][3],
                        kq[ks * 2], kq[ks * 2 + 1]);
        }

        // ---- softmax (registers) ----
        const bool mask_tile = causal && (kb >= qb * 2);
        float smax0 = -INFINITY, smax1 = -INFINITY;
        #pragma unroll
        for (int nt = 0; nt < 8; nt++) {
            const int col = kb * 64 + nt * 8 + 2 * t;
            sa[nt][0] *= 0.125f; sa[nt][1] *= 0.125f;
            sa[nt][2] *= 0.125f; sa[nt][3] *= 0.125f;
            if (mask_tile) {
                if (col     > row0)     sa[nt][0] = -1e9f;
                if (col + 1 > row0)     sa[nt][1] = -1e9f;
                if (col     > row0 + 8) sa[nt][2] = -1e9f;
                if (col + 1 > row0 + 8) sa[nt][3] = -1e9f;
            }
            smax0 = fmaxf(smax0, fmaxf(sa[nt][0], sa[nt][1]));
            smax1 = fmaxf(smax1, fmaxf(sa[nt][2], sa[nt][3]));
        }
        smax0 = fmaxf(smax0, __shfl_xor_sync(0xffffffffu, smax0, 1));
        smax0 = fmaxf(smax0, __shfl_xor_sync(0xffffffffu, smax0, 2));
        smax1 = fmaxf(smax1, __shfl_xor_sync(0xffffffffu, smax1, 1));
        smax1 = fmaxf(smax1, __shfl_xor_sync(0xffffffffu, smax1, 2));

        const float m0n = fmaxf(m0, smax0);
        const float m1n = fmaxf(m1, smax1);
        const float cr0 = __expf(m0 - m0n);
        const float cr1 = __expf(m1 - m1n);
        m0 = m0n; m1 = m1n;

        float ls0 = 0.f, ls1 = 0.f;
        #pragma unroll
        for (int nt = 0; nt < 8; nt++) {
            sa[nt][0] = __expf(sa[nt][0] - m0n);
            sa[nt][1] = __expf(sa[nt][1] - m0n);
            sa[nt][2] = __expf(sa[nt][2] - m1n);
            sa[nt][3] = __expf(sa[nt][3] - m1n);
            ls0 += sa[nt][0] + sa[nt][1];
            ls1 += sa[nt][2] + sa[nt][3];
        }
        ls0 += __shfl_xor_sync(0xffffffffu, ls0, 1);
        ls0 += __shfl_xor_sync(0xffffffffu, ls0, 2);
        ls1 += __shfl_xor_sync(0xffffffffu, ls1, 1);
        ls1 += __shfl_xor_sync(0xffffffffu, ls1, 2);
        l0 = l0 * cr0 + ls0;
        l1 = l1 * cr1 + ls1;

        #pragma unroll
        for (int nt = 0; nt < 8; nt++) {
            oacc[nt][0] *= cr0; oacc[nt][1] *= cr0;
            oacc[nt][2] *= cr1; oacc[nt][3] *= cr1;
        }

        // ---- O += P V : P packs directly into A-fragments ----
        #pragma unroll
        for (int ks = 0; ks < 4; ks++) {
            const unsigned a0 = packh2(sa[2*ks  ][0], sa[2*ks  ][1]);
            const unsigned a1 = packh2(sa[2*ks  ][2], sa[2*ks  ][3]);
            const unsigned a2 = packh2(sa[2*ks+1][0], sa[2*ks+1][1]);
            const unsigned a3 = packh2(sa[2*ks+1][2], sa[2*ks+1][3]);
            #pragma unroll
            for (int dg = 0; dg < 4; dg++) {
                unsigned v0, v1, v2, v3;
                LDSM_X4T(v0, v1, v2, v3, v_base + (ks * 16 * AP + dg * 16) * 2);
                mma_f16(oacc[2*dg    ], a0, a1, a2, a3, v0, v1);
                mma_f16(oacc[2*dg + 1], a0, a1, a2, a3, v2, v3);
            }
        }
    }

    const float inv0 = 1.f / l0;
    const float inv1 = 1.f / l1;
    float* op = O + ((size_t)(b * S_ + row0)) * DM + h * DH;
    #pragma unroll
    for (int nt = 0; nt < 8; nt++) {
        float2 v;
        v.x = oacc[nt][0] * inv0; v.y = oacc[nt][1] * inv0;
        *(float2*)&op[nt * 8 + 2 * t] = v;
        v.x = oacc[nt][2] * inv1; v.y = oacc[nt][3] * inv1;
        *(float2*)&op[(size_t)8 * DM + nt * 8 + 2 * t] = v;
    }
}

// ---------------- residual add + layernorm (fp32 out + fp16 copy) --------
__global__ __launch_bounds__(256)
void ln_kernel(const float* __restrict__ att, const float* __restrict__ resid,
               const float* __restrict__ g, const float* __restrict__ bt,
               float* __restrict__ xout, __half* __restrict__ xh)
{
    const int row = blockIdx.x;
    const int tid = threadIdx.x;

    float4 a = *(const float4*)&att  [(size_t)row * DM + tid * 4];
    float4 r = *(const float4*)&resid[(size_t)row * DM + tid * 4];
    float4 v;
    v.x = a.x + r.x; v.y = a.y + r.y; v.z = a.z + r.z; v.w = a.w + r.w;

    float s1 = v.x + v.y + v.z + v.w;
    float s2 = v.x*v.x + v.y*v.y + v.z*v.z + v.w*v.w;

    __shared__ float sh1[8], sh2[8];
    #pragma unroll
    for (int o = 16; o > 0; o >>= 1) {
        s1 += __shfl_xor_sync(0xffffffffu, s1, o);
        s2 += __shfl_xor_sync(0xffffffffu, s2, o);
    }
    if ((tid & 31) == 0) { sh1[tid >> 5] = s1; sh2[tid >> 5] = s2; }
    __syncthreads();
    float t1 = 0.f, t2 = 0.f;
    #pragma unroll
    for (int i = 0; i < 8; i++) { t1 += sh1[i]; t2 += sh2[i]; }

    const float mu  = t1 * (1.0f / DM);
    const float var = t2 * (1.0f / DM) - mu * mu;
    const float rs  = rsqrtf(var + 1e-5f);

    float4 gg = *(const float4*)&g [tid * 4];
    float4 bb = *(const float4*)&bt[tid * 4];
    float4 o;
    o.x = (v.x - mu) * rs * gg.x + bb.x;
    o.y = (v.y - mu) * rs * gg.y + bb.y;
    o.z = (v.z - mu) * rs * gg.z + bb.z;
    o.w = (v.w - mu) * rs * gg.w + bb.w;
    *(float4*)&xout[(size_t)row * DM + tid * 4] = o;
    uint2 hh;
    hh.x = packh2(o.x, o.y);
    hh.y = packh2(o.z, o.w);
    *(uint2*)&xh[(size_t)row * DM + tid * 4] = hh;
}

// ---------------- launch ---------------------------------------------------
extern "C" void kernel_launch(void* const* d_in, const int* in_sizes, int n_in,
                              void* d_out, int out_size)
{
    const float* q    = (const float*)d_in[0];
    const float* k    = (const float*)d_in[1];
    const float* Wq   = (const float*)d_in[2];
    const float* bq   = (const float*)d_in[3];
    const float* Wk   = (const float*)d_in[4];
    const float* bk   = (const float*)d_in[5];
    const float* Wv   = (const float*)d_in[6];
    const float* bv   = (const float*)d_in[7];
    const float* W1   = (const float*)d_in[8];
    const float* b1   = (const float*)d_in[9];
    const float* W2   = (const float*)d_in[10];
    const float* b2   = (const float*)d_in[11];
    const float* ln_g = (const float*)d_in[12];
    const float* ln_b = (const float*)d_in[13];
    const int*   msk  = (const int*)d_in[14];

    __half *q16, *k16, *wq16, *wk16, *wv16, *w116, *w216, *Qh, *Kh, *Vh, *Xh, *Hh;
    float *Ab, *Xb;
    cudaGetSymbolAddress((void**)&q16,  g_q16);
    cudaGetSymbolAddress((void**)&k16,  g_k16);
    cudaGetSymbolAddress((void**)&wq16, g_wq16);
    cudaGetSymbolAddress((void**)&wk16, g_wk16);
    cudaGetSymbolAddress((void**)&wv16, g_wv16);
    cudaGetSymbolAddress((void**)&w116, g_w116);
    cudaGetSymbolAddress((void**)&w216, g_w216);
    cudaGetSymbolAddress((void**)&Qh,   g_Qh);
    cudaGetSymbolAddress((void**)&Kh,   g_Kh);
    cudaGetSymbolAddress((void**)&Vh,   g_Vh);
    cudaGetSymbolAddress((void**)&Xh,   g_Xh);
    cudaGetSymbolAddress((void**)&Hh,   g_Hh);
    cudaGetSymbolAddress((void**)&Ab,   g_att);
    cudaGetSymbolAddress((void**)&Xb,   g_x);

    cudaFuncSetAttribute(gemm16<0>, cudaFuncAttributeMaxDynamicSharedMemorySize, GSMEM);
    cudaFuncSetAttribute(gemm16<1>, cudaFuncAttributeMaxDynamicSharedMemorySize, GSMEM);
    cudaFuncSetAttribute(gemm16<2>, cudaFuncAttributeMaxDynamicSharedMemorySize, GSMEM);

    // fp32 -> fp16 conversion pass
    f2h<<<(MTOK*DM/4 + 255)/256, 256>>>((const float4*)q,  (uint2*)q16,  MTOK*DM/4);
    f2h<<<(MTOK*DM/4 + 255)/256, 256>>>((const float4*)k,  (uint2*)k16,  MTOK*DM/4);
    f2h<<<(DM*DM/4   + 255)/256, 256>>>((const float4*)Wq, (uint2*)wq16, DM*DM/4);
    f2h<<<(DM*DM/4   + 255)/256, 256>>>((const float4*)Wk, (uint2*)wk16, DM*DM/4);
    f2h<<<(DM*DM/4   + 255)/256, 256>>>((const float4*)Wv, (uint2*)wv16, DM*DM/4);
    f2h<<<(DFF*DM/4  + 255)/256, 256>>>((const float4*)W1, (uint2*)w116, DFF*DM/4);
    f2h<<<(DFF*DM/4  + 255)/256, 256>>>((const float4*)W2, (uint2*)w216, DFF*DM/4);

    // QKV projections (fp16 out)
    gemm16<0><<<dim3(DM / 128, MTOK / 128), 256, GSMEM>>>(q16, wq16, bq, Qh, nullptr, MTOK, DM, DM);
    gemm16<0><<<dim3(DM / 128, MTOK / 128), 256, GSMEM>>>(k16, wk16, bk, Kh, nullptr, MTOK, DM, DM);
    gemm16<0><<<dim3(DM / 128, MTOK / 128), 256, GSMEM>>>(k16, wv16, bv, Vh, nullptr, MTOK, DM, DM);

    // causal attention (fp16 in, fp32 out)
    attn_tc<<<dim3(S_ / 128, H_, B_), 256>>>(Qh, Kh, Vh, Ab, msk);

    // residual + layernorm (fp32 + fp16 outputs)
    ln_kernel<<<MTOK, 256>>>(Ab, q, ln_g, ln_b, Xb, Xh);

    // FFN
    gemm16<1><<<dim3(DFF / 128, MTOK / 128), 256, GSMEM>>>(Xh, w116, b1, Hh, nullptr, MTOK, DFF, DM);
    gemm16<2><<<dim3(DM / 128, MTOK / 128), 256, GSMEM>>>(Hh, w216, b2, d_out, Xb, MTOK, DM, DFF);
}

// round 10
// speedup vs baseline: 4.8587x; 1.0220x over previous
#include <cuda_runtime.h>
#include <cuda_fp16.h>
#include <math.h>
#include <stdint.h>

#define B_    2
#define S_    2048
#define DM    1024
#define H_    16
#define DH    64
#define DFF   4096
#define MTOK  (B_*S_)      // 4096 token rows

// ---------------- scratch (device globals; no allocation) ----------------
__device__ __half g_q16 [MTOK*DM];
__device__ __half g_k16 [MTOK*DM];
__device__ __half g_wq16[DM*DM];
__device__ __half g_wk16[DM*DM];
__device__ __half g_wv16[DM*DM];
__device__ __half g_w116[(size_t)DFF*DM];
__device__ __half g_w216[(size_t)DM*DFF];
__device__ __half g_Qh  [MTOK*DM];
__device__ __half g_Kh  [MTOK*DM];
__device__ __half g_Vh  [MTOK*DM];
__device__ __half g_Xh  [MTOK*DM];
__device__ __half g_Hh  [(size_t)MTOK*DFF];
__device__ float  g_att [MTOK*DM];
__device__ float  g_x   [MTOK*DM];

// ---------------- helpers -------------------------------------------------
__device__ __forceinline__ void mma_f16(float c[4],
                                        unsigned a0, unsigned a1, unsigned a2, unsigned a3,
                                        unsigned b0, unsigned b1) {
    asm volatile("mma.sync.aligned.m16n8k16.row.col.f32.f16.f16.f32 "
                 "{%0,%1,%2,%3}, {%4,%5,%6,%7}, {%8,%9}, {%0,%1,%2,%3};"
                 : "+f"(c[0]), "+f"(c[1]), "+f"(c[2]), "+f"(c[3])
                 : "r"(a0), "r"(a1), "r"(a2), "r"(a3), "r"(b0), "r"(b1));
}

#define LDSM_X4(r0, r1, r2, r3, addr) \
    asm volatile("ldmatrix.sync.aligned.m8n8.x4.shared.b16 {%0,%1,%2,%3}, [%4];" \
                 : "=r"(r0), "=r"(r1), "=r"(r2), "=r"(r3) : "r"(addr))

#define LDSM_X4T(r0, r1, r2, r3, addr) \
    asm volatile("ldmatrix.sync.aligned.m8n8.x4.trans.shared.b16 {%0,%1,%2,%3}, [%4];" \
                 : "=r"(r0), "=r"(r1), "=r"(r2), "=r"(r3) : "r"(addr))

// pack two floats -> f16x2 register (lo = a, hi = b)
__device__ __forceinline__ unsigned packh2(float a, float b) {
    unsigned r;
    asm("cvt.rn.f16x2.f32 %0, %1, %2;" : "=r"(r) : "f"(b), "f"(a));
    return r;
}

// ---------------- fp32 -> fp16 conversion pass ----------------------------
__global__ __launch_bounds__(256)
void f2h(const float4* __restrict__ src, uint2* __restrict__ dst, int n4)
{
    const int i = blockIdx.x * 256 + threadIdx.x;
    if (i < n4) {
        float4 v = src[i];
        uint2 o;
        o.x = packh2(v.x, v.y);
        o.y = packh2(v.z, v.w);
        dst[i] = o;
    }
}

// ---------------- fp16 tensor-core GEMM, NT, CTA tile 128x256 -------------
// C[m,n] = sum_k A[m,k]*B[n,k]. KC=32, double-buffered, 8 warps,
// warp tile 64x64 (2m x 4n warp grid).
// EPI: 0 = +bias -> fp16 out; 1 = gelu(+bias) -> fp16 out; 2 = +bias+res -> fp32 out
#define KC32 32
#define HPW  40                         // pitch 40 halves = 80B = 5*16
#define ABUF (128 * HPW * 2)            // 10240 B
#define BBUF (256 * HPW * 2)            // 20480 B
#define GSMEM (2 * (ABUF + BBUF))       // 61440 B dynamic smem

template<int EPI>
__global__ __launch_bounds__(256, 1)
void gemm16(const __half* __restrict__ A, const __half* __restrict__ Bm,
            const float* __restrict__ bias, void* __restrict__ Cout,
            const float* __restrict__ res, int M, int N, int K)
{
    extern __shared__ char smem[];
    __half* As = (__half*)smem;                      // 2 buffers of 128*HPW
    __half* Bs = (__half*)(smem + 2 * ABUF);         // 2 buffers of 256*HPW

    const int tid  = threadIdx.x;
    const int m0   = blockIdx.y * 128;
    const int n0   = blockIdx.x * 256;
    const int lane = tid & 31;
    const int w    = tid >> 5;
    const int wm   = (w >> 2) * 64;      // 0 or 64
    const int wn   = (w & 3) * 64;       // 0,64,128,192
    const int g    = lane >> 2;
    const int t    = lane & 3;

    float acc[4][8][4];
    #pragma unroll
    for (int i = 0; i < 4; i++)
        #pragma unroll
        for (int j = 0; j < 8; j++)
            #pragma unroll
            for (int u = 0; u < 4; u++) acc[i][j][u] = 0.f;

    const uint32_t sA = (uint32_t)__cvta_generic_to_shared(As);
    const uint32_t sB = (uint32_t)__cvta_generic_to_shared(Bs);
    const uint32_t a_base = sA + (((uint32_t)(wm + (lane & 15))) * HPW + ((lane >> 4) * 8)) * 2;
    const uint32_t b_base = sB + (((uint32_t)(wn + (lane & 7)))  * HPW + ((lane >> 3) * 8)) * 2;

    // staging: A 512 uint4 slots (2/thread), B 1024 slots (4/thread)
    // slot s -> row = s>>2, grp = s&3 (8 halves each; 32 halves per row)
    uint4 ra[2], rb[4];
    const int srow = tid >> 2;
    const int sgrp = tid & 3;

    auto gload = [&](int k0) {
        #pragma unroll
        for (int i = 0; i < 2; i++)
            ra[i] = *(const uint4*)&A [(size_t)(m0 + srow + i * 64) * K + k0 + sgrp * 8];
        #pragma unroll
        for (int i = 0; i < 4; i++)
            rb[i] = *(const uint4*)&Bm[(size_t)(n0 + srow + i * 64) * K + k0 + sgrp * 8];
    };
    auto sts = [&](int buf) {
        __half* pa = As + buf * (128 * HPW);
        __half* pb = Bs + buf * (256 * HPW);
        #pragma unroll
        for (int i = 0; i < 2; i++)
            *(uint4*)&pa[(srow + i * 64) * HPW + sgrp * 8] = ra[i];
        #pragma unroll
        for (int i = 0; i < 4; i++)
            *(uint4*)&pb[(srow + i * 64) * HPW + sgrp * 8] = rb[i];
    };
    auto compute = [&](int buf) {
        const uint32_t boA = (uint32_t)buf * ABUF;
        const uint32_t boB = (uint32_t)buf * BBUF;
        unsigned bq[8][4];
        #pragma unroll
        for (int nt = 0; nt < 8; nt++)
            LDSM_X4(bq[nt][0], bq[nt][1], bq[nt][2], bq[nt][3],
                    b_base + boB + nt * (8 * HPW * 2));
        #pragma unroll
        for (int kh = 0; kh < 2; kh++) {
            unsigned aq[4][4];
            #pragma unroll
            for (int mt = 0; mt < 4; mt++)
                LDSM_X4(aq[mt][0], aq[mt][1], aq[mt][2], aq[mt][3],
                        a_base + boA + mt * (16 * HPW * 2) + kh * 32);
            #pragma unroll
            for (int mt = 0; mt < 4; mt++)
                #pragma unroll
                for (int nt = 0; nt < 8; nt++)
                    mma_f16(acc[mt][nt], aq[mt][0], aq[mt][1], aq[mt][2], aq[mt][3],
                            bq[nt][kh * 2], bq[nt][kh * 2 + 1]);
        }
    };

    const int NC = K / KC32;
    gload(0);
    sts(0);
    __syncthreads();
    for (int c = 0; c < NC; c++) {
        if (c + 1 < NC) gload((c + 1) * KC32);
        compute(c & 1);
        if (c + 1 < NC) sts((c + 1) & 1);
        __syncthreads();
    }

    // epilogue
    #pragma unroll
    for (int mt = 0; mt < 4; mt++) {
        #pragma unroll
        for (int half = 0; half < 2; half++) {
            const int row = m0 + wm + mt * 16 + g + half * 8;
            #pragma unroll
            for (int nt = 0; nt < 8; nt++) {
                const int col = n0 + wn + nt * 8 + 2 * t;
                float v0 = acc[mt][nt][half * 2 + 0] + bias[col];
                float v1 = acc[mt][nt][half * 2 + 1] + bias[col + 1];
                if (EPI == 1) {
                    v0 = 0.5f * v0 * (1.0f + erff(v0 * 0.70710678118654752f));
                    v1 = 0.5f * v1 * (1.0f + erff(v1 * 0.70710678118654752f));
                }
                if (EPI == 2) {
                    v0 += res[(size_t)row * N + col];
                    v1 += res[(size_t)row * N + col + 1];
                    float2 o; o.x = v0; o.y = v1;
                    *(float2*)&((float*)Cout)[(size_t)row * N + col] = o;
                } else {
                    *(unsigned*)&((__half*)Cout)[(size_t)row * N + col] = packh2(v0, v1);
                }
            }
        }
    }
}

// ---------------- fp16 tensor-core causal flash attention ----------------
// CTA: 128 q rows, 8 warps (16 rows each). kv tiles of 64. fp16 Q/K/V in gmem.
#define AP 72

__global__ __launch_bounds__(256)
void attn_tc(const __half* __restrict__ Q, const __half* __restrict__ K,
             const __half* __restrict__ V, float* __restrict__ O,
             const int* __restrict__ use_mask)
{
    __shared__ __half Ks[64 * AP];
    __shared__ __half Vs[64 * AP];

    const int tid  = threadIdx.x;
    const int lane = tid & 31;
    const int w    = tid >> 5;
    const int g    = lane >> 2;
    const int t    = lane & 3;
    const int qb   = (gridDim.x - 1) - blockIdx.x;   // heavy q-blocks first
    const int h    = blockIdx.y;
    const int b    = blockIdx.z;
    const int q0   = qb * 128;
    const int causal = use_mask[0];
    const int row0 = q0 + w * 16 + g;                // rows row0, row0+8

    // Q fragments: direct fp16 loads (pairs are contiguous)
    unsigned qf[4][4];
    {
        const __half* qp  = Q + ((size_t)(b * S_ + row0)) * DM + h * DH;
        const __half* qp8 = qp + 8 * DM;
        #pragma unroll
        for (int ks = 0; ks < 4; ks++) {
            const int c = ks * 16 + 2 * t;
            qf[ks][0] = *(const unsigned*)&qp [c];
            qf[ks][1] = *(const unsigned*)&qp8[c];
            qf[ks][2] = *(const unsigned*)&qp [c + 8];
            qf[ks][3] = *(const unsigned*)&qp8[c + 8];
        }
    }

    const uint32_t sK = (uint32_t)__cvta_generic_to_shared(&Ks[0]);
    const uint32_t sV = (uint32_t)__cvta_generic_to_shared(&Vs[0]);
    const uint32_t k_base = sK + (((uint32_t)(lane & 7)) * AP + ((lane >> 3) * 8)) * 2;
    const uint32_t v_base = sV + (((uint32_t)(lane & 15)) * AP + ((lane >> 4) * 8)) * 2;

    float m0 = -INFINITY, m1 = -INFINITY, l0 = 0.f, l1 = 0.f;
    float oacc[8][4];
    #pragma unroll
    for (int nt = 0; nt < 8; nt++)
        #pragma unroll
        for (int u = 0; u < 4; u++) oacc[nt][u] = 0.f;

    const int nkb = causal ? (qb * 2 + 2) : (S_ / 64);

    // staging: slot s = tid + i*256 (i<2) -> row = s>>3 (0..63), grp = s&7 (8 halves)
    const int sr = tid >> 3;
    const int sg = tid & 7;
    uint4 pk[2], pv[2];
    #pragma unroll
    for (int i = 0; i < 2; i++) {
        size_t src = ((size_t)(b * S_ + sr + i * 32)) * DM + h * DH + sg * 8;
        pk[i] = *(const uint4*)&K[src];
        pv[i] = *(const uint4*)&V[src];
    }

    for (int kb = 0; kb < nkb; kb++) {
        __syncthreads();   // prior tile fully consumed
        #pragma unroll
        for (int i = 0; i < 2; i++) {
            const int idx = (sr + i * 32) * AP + sg * 8;
            *(uint4*)&Ks[idx] = pk[i];
            *(uint4*)&Vs[idx] = pv[i];
        }
        __syncthreads();

        // prefetch next tile
        if (kb + 1 < nkb) {
            #pragma unroll
            for (int i = 0; i < 2; i++) {
                size_t src = ((size_t)(b * S_ + (kb + 1) * 64 + sr + i * 32)) * DM + h * DH + sg * 8;
                pk[i] = *(const uint4*)&K[src];
                pv[i] = *(const uint4*)&V[src];
            }
        }

        // ---- S = Q K^T (16x64 per warp) ----
        float sa[8][4];
        #pragma unroll
        for (int nt = 0; nt < 8; nt++)
            #pragma unroll
            for (int u = 0; u < 4; u++) sa[nt][u] = 0.f;

        #pragma unroll
        for (int nt = 0; nt < 8; nt++) {
            unsigned kq[8];
            LDSM_X4(kq[0], kq[1], kq[2], kq[3], k_base + (nt * 8 * AP) * 2);
            LDSM_X4(kq[4], kq[5], kq[6], kq[7], k_base + (nt * 8 * AP) * 2 + 64);
            #pragma unroll
            for (int ks = 0; ks < 4; ks++)
                mma_f16(sa[nt], qf[ks][0], qf[ks][1], qf[ks][2], qf[ks][3],
                        kq[ks * 2], kq[ks * 2 + 1]);
        }

        // ---- softmax (registers) ----
        const bool mask_tile = causal && (kb >= qb * 2);
        float smax0 = -INFINITY, smax1 = -INFINITY;
        #pragma unroll
        for (int nt = 0; nt < 8; nt++) {
            const int col = kb * 64 + nt * 8 + 2 * t;
            sa[nt][0] *= 0.125f; sa[nt][1] *= 0.125f;
            sa[nt][2] *= 0.125f; sa[nt][3] *= 0.125f;
            if (mask_tile) {
                if (col     > row0)     sa[nt][0] = -1e9f;
                if (col + 1 > row0)     sa[nt][1] = -1e9f;
                if (col     > row0 + 8) sa[nt][2] = -1e9f;
                if (col + 1 > row0 + 8) sa[nt][3] = -1e9f;
            }
            smax0 = fmaxf(smax0, fmaxf(sa[nt][0], sa[nt][1]));
            smax1 = fmaxf(smax1, fmaxf(sa[nt][2], sa[nt][3]));
        }
        smax0 = fmaxf(smax0, __shfl_xor_sync(0xffffffffu, smax0, 1));
        smax0 = fmaxf(smax0, __shfl_xor_sync(0xffffffffu, smax0, 2));
        smax1 = fmaxf(smax1, __shfl_xor_sync(0xffffffffu, smax1, 1));
        smax1 = fmaxf(smax1, __shfl_xor_sync(0xffffffffu, smax1, 2));

        const float m0n = fmaxf(m0, smax0);
        const float m1n = fmaxf(m1, smax1);
        const float cr0 = __expf(m0 - m0n);
        const float cr1 = __expf(m1 - m1n);
        m0 = m0n; m1 = m1n;

        float ls0 = 0.f, ls1 = 0.f;
        #pragma unroll
        for (int nt = 0; nt < 8; nt++) {
            sa[nt][0] = __expf(sa[nt][0] - m0n);
            sa[nt][1] = __expf(sa[nt][1] - m0n);
            sa[nt][2] = __expf(sa[nt][2] - m1n);
            sa[nt][3] = __expf(sa[nt][3] - m1n);
            ls0 += sa[nt][0] + sa[nt][1];
            ls1 += sa[nt][2] + sa[nt][3];
        }
        ls0 += __shfl_xor_sync(0xffffffffu, ls0, 1);
        ls0 += __shfl_xor_sync(0xffffffffu, ls0, 2);
        ls1 += __shfl_xor_sync(0xffffffffu, ls1, 1);
        ls1 += __shfl_xor_sync(0xffffffffu, ls1, 2);
        l0 = l0 * cr0 + ls0;
        l1 = l1 * cr1 + ls1;

        #pragma unroll
        for (int nt = 0; nt < 8; nt++) {
            oacc[nt][0] *= cr0; oacc[nt][1] *= cr0;
            oacc[nt][2] *= cr1; oacc[nt][3] *= cr1;
        }

        // ---- O += P V : P packs directly into A-fragments ----
        #pragma unroll
        for (int ks = 0; ks < 4; ks++) {
            const unsigned a0 = packh2(sa[2*ks  ][0], sa[2*ks  ][1]);
            const unsigned a1 = packh2(sa[2*ks  ][2], sa[2*ks  ][3]);
            const unsigned a2 = packh2(sa[2*ks+1][0], sa[2*ks+1][1]);
            const unsigned a3 = packh2(sa[2*ks+1][2], sa[2*ks+1][3]);
            #pragma unroll
            for (int dg = 0; dg < 4; dg++) {
                unsigned v0, v1, v2, v3;
                LDSM_X4T(v0, v1, v2, v3, v_base + (ks * 16 * AP + dg * 16) * 2);
                mma_f16(oacc[2*dg    ], a0, a1, a2, a3, v0, v1);
                mma_f16(oacc[2*dg + 1], a0, a1, a2, a3, v2, v3);
            }
        }
    }

    const float inv0 = 1.f / l0;
    const float inv1 = 1.f / l1;
    float* op = O + ((size_t)(b * S_ + row0)) * DM + h * DH;
    #pragma unroll
    for (int nt = 0; nt < 8; nt++) {
        float2 v;
        v.x = oacc[nt][0] * inv0; v.y = oacc[nt][1] * inv0;
        *(float2*)&op[nt * 8 + 2 * t] = v;
        v.x = oacc[nt][2] * inv1; v.y = oacc[nt][3] * inv1;
        *(float2*)&op[(size_t)8 * DM + nt * 8 + 2 * t] = v;
    }
}

// ---------------- residual add + layernorm (fp32 out + fp16 copy) --------
__global__ __launch_bounds__(256)
void ln_kernel(const float* __restrict__ att, const float* __restrict__ resid,
               const float* __restrict__ g, const float* __restrict__ bt,
               float* __restrict__ xout, __half* __restrict__ xh)
{
    const int row = blockIdx.x;
    const int tid = threadIdx.x;

    float4 a = *(const float4*)&att  [(size_t)row * DM + tid * 4];
    float4 r = *(const float4*)&resid[(size_t)row * DM + tid * 4];
    float4 v;
    v.x = a.x + r.x; v.y = a.y + r.y; v.z = a.z + r.z; v.w = a.w + r.w;

    float s1 = v.x + v.y + v.z + v.w;
    float s2 = v.x*v.x + v.y*v.y + v.z*v.z + v.w*v.w;

    __shared__ float sh1[8], sh2[8];
    #pragma unroll
    for (int o = 16; o > 0; o >>= 1) {
        s1 += __shfl_xor_sync(0xffffffffu, s1, o);
        s2 += __shfl_xor_sync(0xffffffffu, s2, o);
    }
    if ((tid & 31) == 0) { sh1[tid >> 5] = s1; sh2[tid >> 5] = s2; }
    __syncthreads();
    float t1 = 0.f, t2 = 0.f;
    #pragma unroll
    for (int i = 0; i < 8; i++) { t1 += sh1[i]; t2 += sh2[i]; }

    const float mu  = t1 * (1.0f / DM);
    const float var = t2 * (1.0f / DM) - mu * mu;
    const float rs  = rsqrtf(var + 1e-5f);

    float4 gg = *(const float4*)&g [tid * 4];
    float4 bb = *(const float4*)&bt[tid * 4];
    float4 o;
    o.x = (v.x - mu) * rs * gg.x + bb.x;
    o.y = (v.y - mu) * rs * gg.y + bb.y;
    o.z = (v.z - mu) * rs * gg.z + bb.z;
    o.w = (v.w - mu) * rs * gg.w + bb.w;
    *(float4*)&xout[(size_t)row * DM + tid * 4] = o;
    uint2 hh;
    hh.x = packh2(o.x, o.y);
    hh.y = packh2(o.z, o.w);
    *(uint2*)&xh[(size_t)row * DM + tid * 4] = hh;
}

// ---------------- launch ---------------------------------------------------
extern "C" void kernel_launch(void* const* d_in, const int* in_sizes, int n_in,
                              void* d_out, int out_size)
{
    const float* q    = (const float*)d_in[0];
    const float* k    = (const float*)d_in[1];
    const float* Wq   = (const float*)d_in[2];
    const float* bq   = (const float*)d_in[3];
    const float* Wk   = (const float*)d_in[4];
    const float* bk   = (const float*)d_in[5];
    const float* Wv   = (const float*)d_in[6];
    const float* bv   = (const float*)d_in[7];
    const float* W1   = (const float*)d_in[8];
    const float* b1   = (const float*)d_in[9];
    const float* W2   = (const float*)d_in[10];
    const float* b2   = (const float*)d_in[11];
    const float* ln_g = (const float*)d_in[12];
    const float* ln_b = (const float*)d_in[13];
    const int*   msk  = (const int*)d_in[14];

    __half *q16, *k16, *wq16, *wk16, *wv16, *w116, *w216, *Qh, *Kh, *Vh, *Xh, *Hh;
    float *Ab, *Xb;
    cudaGetSymbolAddress((void**)&q16,  g_q16);
    cudaGetSymbolAddress((void**)&k16,  g_k16);
    cudaGetSymbolAddress((void**)&wq16, g_wq16);
    cudaGetSymbolAddress((void**)&wk16, g_wk16);
    cudaGetSymbolAddress((void**)&wv16, g_wv16);
    cudaGetSymbolAddress((void**)&w116, g_w116);
    cudaGetSymbolAddress((void**)&w216, g_w216);
    cudaGetSymbolAddress((void**)&Qh,   g_Qh);
    cudaGetSymbolAddress((void**)&Kh,   g_Kh);
    cudaGetSymbolAddress((void**)&Vh,   g_Vh);
    cudaGetSymbolAddress((void**)&Xh,   g_Xh);
    cudaGetSymbolAddress((void**)&Hh,   g_Hh);
    cudaGetSymbolAddress((void**)&Ab,   g_att);
    cudaGetSymbolAddress((void**)&Xb,   g_x);

    cudaFuncSetAttribute(gemm16<0>, cudaFuncAttributeMaxDynamicSharedMemorySize, GSMEM);
    cudaFuncSetAttribute(gemm16<1>, cudaFuncAttributeMaxDynamicSharedMemorySize, GSMEM);
    cudaFuncSetAttribute(gemm16<2>, cudaFuncAttributeMaxDynamicSharedMemorySize, GSMEM);

    // fp32 -> fp16 conversion pass
    f2h<<<(MTOK*DM/4 + 255)/256, 256>>>((const float4*)q,  (uint2*)q16,  MTOK*DM/4);
    f2h<<<(MTOK*DM/4 + 255)/256, 256>>>((const float4*)k,  (uint2*)k16,  MTOK*DM/4);
    f2h<<<(DM*DM/4   + 255)/256, 256>>>((const float4*)Wq, (uint2*)wq16, DM*DM/4);
    f2h<<<(DM*DM/4   + 255)/256, 256>>>((const float4*)Wk, (uint2*)wk16, DM*DM/4);
    f2h<<<(DM*DM/4   + 255)/256, 256>>>((const float4*)Wv, (uint2*)wv16, DM*DM/4);
    f2h<<<(DFF*DM/4  + 255)/256, 256>>>((const float4*)W1, (uint2*)w116, DFF*DM/4);
    f2h<<<(DFF*DM/4  + 255)/256, 256>>>((const float4*)W2, (uint2*)w216, DFF*DM/4);

    // QKV projections (fp16 out)
    gemm16<0><<<dim3(DM / 256, MTOK / 128), 256, GSMEM>>>(q16, wq16, bq, Qh, nullptr, MTOK, DM, DM);
    gemm16<0><<<dim3(DM / 256, MTOK / 128), 256, GSMEM>>>(k16, wk16, bk, Kh, nullptr, MTOK, DM, DM);
    gemm16<0><<<dim3(DM / 256, MTOK / 128), 256, GSMEM>>>(k16, wv16, bv, Vh, nullptr, MTOK, DM, DM);

    // causal attention (fp16 in, fp32 out)
    attn_tc<<<dim3(S_ / 128, H_, B_), 256>>>(Qh, Kh, Vh, Ab, msk);

    // residual + layernorm (fp32 + fp16 outputs)
    ln_kernel<<<MTOK, 256>>>(Ab, q, ln_g, ln_b, Xb, Xh);

    // FFN
    gemm16<1><<<dim3(DFF / 256, MTOK / 128), 256, GSMEM>>>(Xh, w116, b1, Hh, nullptr, MTOK, DFF, DM);
    gemm16<2><<<dim3(DM / 256, MTOK / 128), 256, GSMEM>>>(Hh, w216, b2, d_out, Xb, MTOK, DM, DFF);
}

// round 11
// speedup vs baseline: 5.1084x; 1.0514x over previous
#include <cuda_runtime.h>
#include <cuda_fp16.h>
#include <math.h>
#include <stdint.h>

#define B_    2
#define S_    2048
#define DM    1024
#define H_    16
#define DH    64
#define DFF   4096
#define MTOK  (B_*S_)      // 4096 token rows

// ---------------- scratch (device globals; no allocation) ----------------
__device__ __half g_q16 [MTOK*DM];
__device__ __half g_k16 [MTOK*DM];
__device__ __half g_wq16[DM*DM];
__device__ __half g_wk16[DM*DM];
__device__ __half g_wv16[DM*DM];
__device__ __half g_w116[(size_t)DFF*DM];
__device__ __half g_w216[(size_t)DM*DFF];
__device__ __half g_Qh  [MTOK*DM];
__device__ __half g_Kh  [MTOK*DM];
__device__ __half g_Vh  [MTOK*DM];
__device__ __half g_Xh  [MTOK*DM];
__device__ __half g_Hh  [(size_t)MTOK*DFF];
__device__ float  g_att [MTOK*DM];
__device__ float  g_x   [MTOK*DM];

// ---------------- helpers -------------------------------------------------
__device__ __forceinline__ void mma_f16(float c[4],
                                        unsigned a0, unsigned a1, unsigned a2, unsigned a3,
                                        unsigned b0, unsigned b1) {
    asm volatile("mma.sync.aligned.m16n8k16.row.col.f32.f16.f16.f32 "
                 "{%0,%1,%2,%3}, {%4,%5,%6,%7}, {%8,%9}, {%0,%1,%2,%3};"
                 : "+f"(c[0]), "+f"(c[1]), "+f"(c[2]), "+f"(c[3])
                 : "r"(a0), "r"(a1), "r"(a2), "r"(a3), "r"(b0), "r"(b1));
}

#define LDSM_X4(r0, r1, r2, r3, addr) \
    asm volatile("ldmatrix.sync.aligned.m8n8.x4.shared.b16 {%0,%1,%2,%3}, [%4];" \
                 : "=r"(r0), "=r"(r1), "=r"(r2), "=r"(r3) : "r"(addr))

#define LDSM_X4T(r0, r1, r2, r3, addr) \
    asm volatile("ldmatrix.sync.aligned.m8n8.x4.trans.shared.b16 {%0,%1,%2,%3}, [%4];" \
                 : "=r"(r0), "=r"(r1), "=r"(r2), "=r"(r3) : "r"(addr))

#define CP_ASYNC16(dst, src) \
    asm volatile("cp.async.cg.shared.global [%0], [%1], 16;" :: "r"(dst), "l"(src))
#define CP_COMMIT() asm volatile("cp.async.commit_group;" ::: "memory")
#define CP_WAIT1()  asm volatile("cp.async.wait_group 1;" ::: "memory")

// pack two floats -> f16x2 register (lo = a, hi = b)
__device__ __forceinline__ unsigned packh2(float a, float b) {
    unsigned r;
    asm("cvt.rn.f16x2.f32 %0, %1, %2;" : "=r"(r) : "f"(b), "f"(a));
    return r;
}

// ---------------- fused fp32 -> fp16 conversion (all 7 tensors) ----------
// block segments (256 float4 per block):
// q:4096 | k:4096 | Wq:1024 | Wk:1024 | Wv:1024 | W1:4096 | W2:4096 = 19456
__global__ __launch_bounds__(256)
void f2h_all(const float4* __restrict__ q,  const float4* __restrict__ k,
             const float4* __restrict__ wq, const float4* __restrict__ wk,
             const float4* __restrict__ wv, const float4* __restrict__ w1,
             const float4* __restrict__ w2,
             uint2* __restrict__ q16,  uint2* __restrict__ k16,
             uint2* __restrict__ wq16, uint2* __restrict__ wk16,
             uint2* __restrict__ wv16, uint2* __restrict__ w116,
             uint2* __restrict__ w216)
{
    const int bx = blockIdx.x;
    const float4* src; uint2* dst; int off;
    if      (bx <  4096) { src = q;  dst = q16;  off = bx; }
    else if (bx <  8192) { src = k;  dst = k16;  off = bx - 4096; }
    else if (bx <  9216) { src = wq; dst = wq16; off = bx - 8192; }
    else if (bx < 10240) { src = wk; dst = wk16; off = bx - 9216; }
    else if (bx < 11264) { src = wv; dst = wv16; off = bx - 10240; }
    else if (bx < 15360) { src = w1; dst = w116; off = bx - 11264; }
    else                 { src = w2; dst = w216; off = bx - 15360; }
    const int i = off * 256 + threadIdx.x;
    float4 v = src[i];
    uint2 o;
    o.x = packh2(v.x, v.y);
    o.y = packh2(v.z, v.w);
    dst[i] = o;
}

// ---------------- fp16 tensor-core GEMM, NT, CTA tile 128x256 (R10) ------
#define KC32 32
#define HPW  40                         // pitch 40 halves = 80B = 5*16
#define ABUF (128 * HPW * 2)            // 10240 B
#define BBUF (256 * HPW * 2)            // 20480 B
#define GSMEM (2 * (ABUF + BBUF))       // 61440 B dynamic smem

template<int EPI>
__global__ __launch_bounds__(256, 1)
void gemm16(const __half* __restrict__ A, const __half* __restrict__ Bm,
            const float* __restrict__ bias, void* __restrict__ Cout,
            const float* __restrict__ res, int M, int N, int K)
{
    extern __shared__ char smem[];
    __half* As = (__half*)smem;
    __half* Bs = (__half*)(smem + 2 * ABUF);

    const int tid  = threadIdx.x;
    const int m0   = blockIdx.y * 128;
    const int n0   = blockIdx.x * 256;
    const int lane = tid & 31;
    const int w    = tid >> 5;
    const int wm   = (w >> 2) * 64;
    const int wn   = (w & 3) * 64;
    const int g    = lane >> 2;
    const int t    = lane & 3;

    float acc[4][8][4];
    #pragma unroll
    for (int i = 0; i < 4; i++)
        #pragma unroll
        for (int j = 0; j < 8; j++)
            #pragma unroll
            for (int u = 0; u < 4; u++) acc[i][j][u] = 0.f;

    const uint32_t sA = (uint32_t)__cvta_generic_to_shared(As);
    const uint32_t sB = (uint32_t)__cvta_generic_to_shared(Bs);
    const uint32_t a_base = sA + (((uint32_t)(wm + (lane & 15))) * HPW + ((lane >> 4) * 8)) * 2;
    const uint32_t b_base = sB + (((uint32_t)(wn + (lane & 7)))  * HPW + ((lane >> 3) * 8)) * 2;

    uint4 ra[2], rb[4];
    const int srow = tid >> 2;
    const int sgrp = tid & 3;

    auto gload = [&](int k0) {
        #pragma unroll
        for (int i = 0; i < 2; i++)
            ra[i] = *(const uint4*)&A [(size_t)(m0 + srow + i * 64) * K + k0 + sgrp * 8];
        #pragma unroll
        for (int i = 0; i < 4; i++)
            rb[i] = *(const uint4*)&Bm[(size_t)(n0 + srow + i * 64) * K + k0 + sgrp * 8];
    };
    auto sts = [&](int buf) {
        __half* pa = As + buf * (128 * HPW);
        __half* pb = Bs + buf * (256 * HPW);
        #pragma unroll
        for (int i = 0; i < 2; i++)
            *(uint4*)&pa[(srow + i * 64) * HPW + sgrp * 8] = ra[i];
        #pragma unroll
        for (int i = 0; i < 4; i++)
            *(uint4*)&pb[(srow + i * 64) * HPW + sgrp * 8] = rb[i];
    };
    auto compute = [&](int buf) {
        const uint32_t boA = (uint32_t)buf * ABUF;
        const uint32_t boB = (uint32_t)buf * BBUF;
        unsigned bq[8][4];
        #pragma unroll
        for (int nt = 0; nt < 8; nt++)
            LDSM_X4(bq[nt][0], bq[nt][1], bq[nt][2], bq[nt][3],
                    b_base + boB + nt * (8 * HPW * 2));
        #pragma unroll
        for (int kh = 0; kh < 2; kh++) {
            unsigned aq[4][4];
            #pragma unroll
            for (int mt = 0; mt < 4; mt++)
                LDSM_X4(aq[mt][0], aq[mt][1], aq[mt][2], aq[mt][3],
                        a_base + boA + mt * (16 * HPW * 2) + kh * 32);
            #pragma unroll
            for (int mt = 0; mt < 4; mt++)
                #pragma unroll
                for (int nt = 0; nt < 8; nt++)
                    mma_f16(acc[mt][nt], aq[mt][0], aq[mt][1], aq[mt][2], aq[mt][3],
                            bq[nt][kh * 2], bq[nt][kh * 2 + 1]);
        }
    };

    const int NC = K / KC32;
    gload(0);
    sts(0);
    __syncthreads();
    for (int c = 0; c < NC; c++) {
        if (c + 1 < NC) gload((c + 1) * KC32);
        compute(c & 1);
        if (c + 1 < NC) sts((c + 1) & 1);
        __syncthreads();
    }

    #pragma unroll
    for (int mt = 0; mt < 4; mt++) {
        #pragma unroll
        for (int half = 0; half < 2; half++) {
            const int row = m0 + wm + mt * 16 + g + half * 8;
            #pragma unroll
            for (int nt = 0; nt < 8; nt++) {
                const int col = n0 + wn + nt * 8 + 2 * t;
                float v0 = acc[mt][nt][half * 2 + 0] + bias[col];
                float v1 = acc[mt][nt][half * 2 + 1] + bias[col + 1];
                if (EPI == 1) {
                    v0 = 0.5f * v0 * (1.0f + erff(v0 * 0.70710678118654752f));
                    v1 = 0.5f * v1 * (1.0f + erff(v1 * 0.70710678118654752f));
                }
                if (EPI == 2) {
                    v0 += res[(size_t)row * N + col];
                    v1 += res[(size_t)row * N + col + 1];
                    float2 o; o.x = v0; o.y = v1;
                    *(float2*)&((float*)Cout)[(size_t)row * N + col] = o;
                } else {
                    *(unsigned*)&((__half*)Cout)[(size_t)row * N + col] = packh2(v0, v1);
                }
            }
        }
    }
}

// ---------------- fp16 tensor-core causal flash attention ----------------
// CTA: 64 q rows, 4 warps (16 rows each), cp.async double-buffered kv tiles.
#define AP 72
#define ATILE (64 * AP)   // halves per tile

__global__ __launch_bounds__(128, 3)
void attn_tc(const __half* __restrict__ Q, const __half* __restrict__ K,
             const __half* __restrict__ V, float* __restrict__ O,
             const int* __restrict__ use_mask)
{
    __shared__ __half Ks[2][ATILE];
    __shared__ __half Vs[2][ATILE];

    const int tid  = threadIdx.x;
    const int lane = tid & 31;
    const int w    = tid >> 5;                       // 0..3
    const int g    = lane >> 2;
    const int t    = lane & 3;
    const int qb   = (gridDim.x - 1) - blockIdx.x;   // heavy q-blocks first
    const int h    = blockIdx.y;
    const int b    = blockIdx.z;
    const int q0   = qb * 64;
    const int causal = use_mask[0];
    const int row0 = q0 + w * 16 + g;                // rows row0, row0+8

    // Q fragments (fp16 A-layout)
    unsigned qf[4][4];
    {
        const __half* qp  = Q + ((size_t)(b * S_ + row0)) * DM + h * DH;
        const __half* qp8 = qp + 8 * DM;
        #pragma unroll
        for (int ks = 0; ks < 4; ks++) {
            const int c = ks * 16 + 2 * t;
            qf[ks][0] = *(const unsigned*)&qp [c];
            qf[ks][1] = *(const unsigned*)&qp8[c];
            qf[ks][2] = *(const unsigned*)&qp [c + 8];
            qf[ks][3] = *(const unsigned*)&qp8[c + 8];
        }
    }

    const uint32_t sK = (uint32_t)__cvta_generic_to_shared(&Ks[0][0]);
    const uint32_t sV = (uint32_t)__cvta_generic_to_shared(&Vs[0][0]);
    const uint32_t k_frag = sK + (((uint32_t)(lane & 7))  * AP + ((lane >> 3) * 8)) * 2;
    const uint32_t v_frag = sV + (((uint32_t)(lane & 15)) * AP + ((lane >> 4) * 8)) * 2;

    // cp.async staging: slot s = tid + i*128 (i<4) -> row = s>>3, grp = s&7
    const int sr = tid >> 3;       // rows sr, sr+16, sr+32, sr+48
    const int sg = tid & 7;
    const uint32_t kdst = sK + ((uint32_t)(sr * AP + sg * 8)) * 2;
    const uint32_t vdst = sV + ((uint32_t)(sr * AP + sg * 8)) * 2;
    const __half* ksrc = K + ((size_t)(b * S_) + sr) * DM + h * DH + sg * 8;
    const __half* vsrc = V + ((size_t)(b * S_) + sr) * DM + h * DH + sg * 8;

    auto issue_tile = [&](int kb, int buf) {
        const uint32_t bo = (uint32_t)buf * (ATILE * 2);
        const size_t go = (size_t)(kb * 64) * DM;
        #pragma unroll
        for (int i = 0; i < 4; i++) {
            const uint32_t so = (uint32_t)(i * 16 * AP) * 2;
            const size_t gg = go + (size_t)(i * 16) * DM;
            CP_ASYNC16(kdst + bo + so, ksrc + gg);
            CP_ASYNC16(vdst + bo + so, vsrc + gg);
        }
    };

    float m0 = -INFINITY, m1 = -INFINITY, l0 = 0.f, l1 = 0.f;
    float oacc[8][4];
    #pragma unroll
    for (int nt = 0; nt < 8; nt++)
        #pragma unroll
        for (int u = 0; u < 4; u++) oacc[nt][u] = 0.f;

    const int nkb = causal ? (qb + 1) : (S_ / 64);

    // prologue: two tiles in flight
    issue_tile(0, 0);
    CP_COMMIT();
    if (nkb > 1) issue_tile(1, 1);
    CP_COMMIT();

    for (int kb = 0; kb < nkb; kb++) {
        const int buf = kb & 1;
        CP_WAIT1();
        __syncthreads();

        const uint32_t bo = (uint32_t)buf * (ATILE * 2);

        // ---- S = Q K^T (16x64 per warp) ----
        float sa[8][4];
        #pragma unroll
        for (int nt = 0; nt < 8; nt++)
            #pragma unroll
            for (int u = 0; u < 4; u++) sa[nt][u] = 0.f;

        #pragma unroll
        for (int nt = 0; nt < 8; nt++) {
            unsigned kq[8];
            LDSM_X4(kq[0], kq[1], kq[2], kq[3], k_frag + bo + (nt * 8 * AP) * 2);
            LDSM_X4(kq[4], kq[5], kq[6], kq[7], k_frag + bo + (nt * 8 * AP) * 2 + 64);
            #pragma unroll
            for (int ks = 0; ks < 4; ks++)
                mma_f16(sa[nt], qf[ks][0], qf[ks][1], qf[ks][2], qf[ks][3],
                        kq[ks * 2], kq[ks * 2 + 1]);
        }

        // ---- softmax (registers) ----
        const bool mask_tile = causal && (kb == qb);
        float smax0 = -INFINITY, smax1 = -INFINITY;
        #pragma unroll
        for (int nt = 0; nt < 8; nt++) {
            const int col = kb * 64 + nt * 8 + 2 * t;
            sa[nt][0] *= 0.125f; sa[nt][1] *= 0.125f;
            sa[nt][2] *= 0.125f; sa[nt][3] *= 0.125f;
            if (mask_tile) {
                if (col     > row0)     sa[nt][0] = -1e9f;
                if (col + 1 > row0)     sa[nt][1] = -1e9f;
                if (col     > row0 + 8) sa[nt][2] = -1e9f;
                if (col + 1 > row0 + 8) sa[nt][3] = -1e9f;
            }
            smax0 = fmaxf(smax0, fmaxf(sa[nt][0], sa[nt][1]));
            smax1 = fmaxf(smax1, fmaxf(sa[nt][2], sa[nt][3]));
        }
        smax0 = fmaxf(smax0, __shfl_xor_sync(0xffffffffu, smax0, 1));
        smax0 = fmaxf(smax0, __shfl_xor_sync(0xffffffffu, smax0, 2));
        smax1 = fmaxf(smax1, __shfl_xor_sync(0xffffffffu, smax1, 1));
        smax1 = fmaxf(smax1, __shfl_xor_sync(0xffffffffu, smax1, 2));

        const float m0n = fmaxf(m0, smax0);
        const float m1n = fmaxf(m1, smax1);
        const float cr0 = __expf(m0 - m0n);
        const float cr1 = __expf(m1 - m1n);
        m0 = m0n; m1 = m1n;

        float ls0 = 0.f, ls1 = 0.f;
        #pragma unroll
        for (int nt = 0; nt < 8; nt++) {
            sa[nt][0] = __expf(sa[nt][0] - m0n);
            sa[nt][1] = __expf(sa[nt][1] - m0n);
            sa[nt][2] = __expf(sa[nt][2] - m1n);
            sa[nt][3] = __expf(sa[nt][3] - m1n);
            ls0 += sa[nt][0] + sa[nt][1];
            ls1 += sa[nt][2] + sa[nt][3];
        }
        ls0 += __shfl_xor_sync(0xffffffffu, ls0, 1);
        ls0 += __shfl_xor_sync(0xffffffffu, ls0, 2);
        ls1 += __shfl_xor_sync(0xffffffffu, ls1, 1);
        ls1 += __shfl_xor_sync(0xffffffffu, ls1, 2);
        l0 = l0 * cr0 + ls0;
        l1 = l1 * cr1 + ls1;

        #pragma unroll
        for (int nt = 0; nt < 8; nt++) {
            oacc[nt][0] *= cr0; oacc[nt][1] *= cr0;
            oacc[nt][2] *= cr1; oacc[nt][3] *= cr1;
        }

        // ---- O += P V : P packs directly into A-fragments ----
        #pragma unroll
        for (int ks = 0; ks < 4; ks++) {
            const unsigned a0 = packh2(sa[2*ks  ][0], sa[2*ks  ][1]);
            const unsigned a1 = packh2(sa[2*ks  ][2], sa[2*ks  ][3]);
            const unsigned a2 = packh2(sa[2*ks+1][0], sa[2*ks+1][1]);
            const unsigned a3 = packh2(sa[2*ks+1][2], sa[2*ks+1][3]);
            #pragma unroll
            for (int dg = 0; dg < 4; dg++) {
                unsigned v0, v1, v2, v3;
                LDSM_X4T(v0, v1, v2, v3, v_frag + bo + (ks * 16 * AP + dg * 16) * 2);
                mma_f16(oacc[2*dg    ], a0, a1, a2, a3, v0, v1);
                mma_f16(oacc[2*dg + 1], a0, a1, a2, a3, v2, v3);
            }
        }

        __syncthreads();                    // buf fully consumed by all warps
        if (kb + 2 < nkb) issue_tile(kb + 2, buf);
        CP_COMMIT();                        // uniform group accounting
    }

    const float inv0 = 1.f / l0;
    const float inv1 = 1.f / l1;
    float* op = O + ((size_t)(b * S_ + row0)) * DM + h * DH;
    #pragma unroll
    for (int nt = 0; nt < 8; nt++) {
        float2 v;
        v.x = oacc[nt][0] * inv0; v.y = oacc[nt][1] * inv0;
        *(float2*)&op[nt * 8 + 2 * t] = v;
        v.x = oacc[nt][2] * inv1; v.y = oacc[nt][3] * inv1;
        *(float2*)&op[(size_t)8 * DM + nt * 8 + 2 * t] = v;
    }
}

// ---------------- residual add + layernorm (fp32 out + fp16 copy) --------
__global__ __launch_bounds__(256)
void ln_kernel(const float* __restrict__ att, const float* __restrict__ resid,
               const float* __restrict__ g, const float* __restrict__ bt,
               float* __restrict__ xout, __half* __restrict__ xh)
{
    const int row = blockIdx.x;
    const int tid = threadIdx.x;

    float4 a = *(const float4*)&att  [(size_t)row * DM + tid * 4];
    float4 r = *(const float4*)&resid[(size_t)row * DM + tid * 4];
    float4 v;
    v.x = a.x + r.x; v.y = a.y + r.y; v.z = a.z + r.z; v.w = a.w + r.w;

    float s1 = v.x + v.y + v.z + v.w;
    float s2 = v.x*v.x + v.y*v.y + v.z*v.z + v.w*v.w;

    __shared__ float sh1[8], sh2[8];
    #pragma unroll
    for (int o = 16; o > 0; o >>= 1) {
        s1 += __shfl_xor_sync(0xffffffffu, s1, o);
        s2 += __shfl_xor_sync(0xffffffffu, s2, o);
    }
    if ((tid & 31) == 0) { sh1[tid >> 5] = s1; sh2[tid >> 5] = s2; }
    __syncthreads();
    float t1 = 0.f, t2 = 0.f;
    #pragma unroll
    for (int i = 0; i < 8; i++) { t1 += sh1[i]; t2 += sh2[i]; }

    const float mu  = t1 * (1.0f / DM);
    const float var = t2 * (1.0f / DM) - mu * mu;
    const float rs  = rsqrtf(var + 1e-5f);

    float4 gg = *(const float4*)&g [tid * 4];
    float4 bb = *(const float4*)&bt[tid * 4];
    float4 o;
    o.x = (v.x - mu) * rs * gg.x + bb.x;
    o.y = (v.y - mu) * rs * gg.y + bb.y;
    o.z = (v.z - mu) * rs * gg.z + bb.z;
    o.w = (v.w - mu) * rs * gg.w + bb.w;
    *(float4*)&xout[(size_t)row * DM + tid * 4] = o;
    uint2 hh;
    hh.x = packh2(o.x, o.y);
    hh.y = packh2(o.z, o.w);
    *(uint2*)&xh[(size_t)row * DM + tid * 4] = hh;
}

// ---------------- launch ---------------------------------------------------
extern "C" void kernel_launch(void* const* d_in, const int* in_sizes, int n_in,
                              void* d_out, int out_size)
{
    const float* q    = (const float*)d_in[0];
    const float* k    = (const float*)d_in[1];
    const float* Wq   = (const float*)d_in[2];
    const float* bq   = (const float*)d_in[3];
    const float* Wk   = (const float*)d_in[4];
    const float* bk   = (const float*)d_in[5];
    const float* Wv   = (const float*)d_in[6];
    const float* bv   = (const float*)d_in[7];
    const float* W1   = (const float*)d_in[8];
    const float* b1   = (const float*)d_in[9];
    const float* W2   = (const float*)d_in[10];
    const float* b2   = (const float*)d_in[11];
    const float* ln_g = (const float*)d_in[12];
    const float* ln_b = (const float*)d_in[13];
    const int*   msk  = (const int*)d_in[14];

    __half *q16, *k16, *wq16, *wk16, *wv16, *w116, *w216, *Qh, *Kh, *Vh, *Xh, *Hh;
    float *Ab, *Xb;
    cudaGetSymbolAddress((void**)&q16,  g_q16);
    cudaGetSymbolAddress((void**)&k16,  g_k16);
    cudaGetSymbolAddress((void**)&wq16, g_wq16);
    cudaGetSymbolAddress((void**)&wk16, g_wk16);
    cudaGetSymbolAddress((void**)&wv16, g_wv16);
    cudaGetSymbolAddress((void**)&w116, g_w116);
    cudaGetSymbolAddress((void**)&w216, g_w216);
    cudaGetSymbolAddress((void**)&Qh,   g_Qh);
    cudaGetSymbolAddress((void**)&Kh,   g_Kh);
    cudaGetSymbolAddress((void**)&Vh,   g_Vh);
    cudaGetSymbolAddress((void**)&Xh,   g_Xh);
    cudaGetSymbolAddress((void**)&Hh,   g_Hh);
    cudaGetSymbolAddress((void**)&Ab,   g_att);
    cudaGetSymbolAddress((void**)&Xb,   g_x);

    cudaFuncSetAttribute(gemm16<0>, cudaFuncAttributeMaxDynamicSharedMemorySize, GSMEM);
    cudaFuncSetAttribute(gemm16<1>, cudaFuncAttributeMaxDynamicSharedMemorySize, GSMEM);
    cudaFuncSetAttribute(gemm16<2>, cudaFuncAttributeMaxDynamicSharedMemorySize, GSMEM);

    // fused fp32 -> fp16 conversion pass
    f2h_all<<<19456, 256>>>((const float4*)q,  (const float4*)k,
                            (const float4*)Wq, (const float4*)Wk,
                            (const float4*)Wv, (const float4*)W1,
                            (const float4*)W2,
                            (uint2*)q16, (uint2*)k16, (uint2*)wq16,
                            (uint2*)wk16, (uint2*)wv16, (uint2*)w116,
                            (uint2*)w216);

    // QKV projections (fp16 out)
    gemm16<0><<<dim3(DM / 256, MTOK / 128), 256, GSMEM>>>(q16, wq16, bq, Qh, nullptr, MTOK, DM, DM);
    gemm16<0><<<dim3(DM / 256, MTOK / 128), 256, GSMEM>>>(k16, wk16, bk, Kh, nullptr, MTOK, DM, DM);
    gemm16<0><<<dim3(DM / 256, MTOK / 128), 256, GSMEM>>>(k16, wv16, bv, Vh, nullptr, MTOK, DM, DM);

    // causal attention (fp16 in, fp32 out)
    attn_tc<<<dim3(S_ / 64, H_, B_), 128>>>(Qh, Kh, Vh, Ab, msk);

    // residual + layernorm (fp32 + fp16 outputs)
    ln_kernel<<<MTOK, 256>>>(Ab, q, ln_g, ln_b, Xb, Xh);

    // FFN
    gemm16<1><<<dim3(DFF / 256, MTOK / 128), 256, GSMEM>>>(Xh, w116, b1, Hh, nullptr, MTOK, DFF, DM);
    gemm16<2><<<dim3(DM / 256, MTOK / 128), 256, GSMEM>>>(Hh, w216, b2, d_out, Xb, MTOK, DM, DFF);
}

// round 12
// speedup vs baseline: 5.7111x; 1.1180x over previous
#include <cuda_runtime.h>
#include <cuda_fp16.h>
#include <math.h>
#include <stdint.h>

#define B_    2
#define S_    2048
#define DM    1024
#define H_    16
#define DH    64
#define DFF   4096
#define MTOK  (B_*S_)      // 4096 token rows

// ---------------- scratch (device globals; no allocation) ----------------
__device__ __half g_q16 [MTOK*DM];
__device__ __half g_k16 [MTOK*DM];
__device__ __half g_wq16[DM*DM];
__device__ __half g_wk16[DM*DM];
__device__ __half g_wv16[DM*DM];
__device__ __half g_w116[(size_t)DFF*DM];
__device__ __half g_w216[(size_t)DM*DFF];
__device__ __half g_Qh  [MTOK*DM];
__device__ __half g_Kh  [MTOK*DM];
__device__ __half g_Vh  [MTOK*DM];
__device__ __half g_Xh  [MTOK*DM];
__device__ __half g_Hh  [(size_t)MTOK*DFF];
__device__ float  g_att [MTOK*DM];
__device__ float  g_x   [MTOK*DM];

// ---------------- helpers -------------------------------------------------
__device__ __forceinline__ void mma_f16(float c[4],
                                        unsigned a0, unsigned a1, unsigned a2, unsigned a3,
                                        unsigned b0, unsigned b1) {
    asm volatile("mma.sync.aligned.m16n8k16.row.col.f32.f16.f16.f32 "
                 "{%0,%1,%2,%3}, {%4,%5,%6,%7}, {%8,%9}, {%0,%1,%2,%3};"
                 : "+f"(c[0]), "+f"(c[1]), "+f"(c[2]), "+f"(c[3])
                 : "r"(a0), "r"(a1), "r"(a2), "r"(a3), "r"(b0), "r"(b1));
}

#define LDSM_X4(r0, r1, r2, r3, addr) \
    asm volatile("ldmatrix.sync.aligned.m8n8.x4.shared.b16 {%0,%1,%2,%3}, [%4];" \
                 : "=r"(r0), "=r"(r1), "=r"(r2), "=r"(r3) : "r"(addr))

#define LDSM_X4T(r0, r1, r2, r3, addr) \
    asm volatile("ldmatrix.sync.aligned.m8n8.x4.trans.shared.b16 {%0,%1,%2,%3}, [%4];" \
                 : "=r"(r0), "=r"(r1), "=r"(r2), "=r"(r3) : "r"(addr))

#define CP_ASYNC16(dst, src) \
    asm volatile("cp.async.cg.shared.global [%0], [%1], 16;" :: "r"(dst), "l"(src))
#define CP_COMMIT() asm volatile("cp.async.commit_group;" ::: "memory")
#define CP_WAIT1()  asm volatile("cp.async.wait_group 1;" ::: "memory")

// pack two floats -> f16x2 register (lo = a, hi = b)
__device__ __forceinline__ unsigned packh2(float a, float b) {
    unsigned r;
    asm("cvt.rn.f16x2.f32 %0, %1, %2;" : "=r"(r) : "f"(b), "f"(a));
    return r;
}

// ---------------- fused fp32 -> fp16 conversion (all 7 tensors) ----------
__global__ __launch_bounds__(256)
void f2h_all(const float4* __restrict__ q,  const float4* __restrict__ k,
             const float4* __restrict__ wq, const float4* __restrict__ wk,
             const float4* __restrict__ wv, const float4* __restrict__ w1,
             const float4* __restrict__ w2,
             uint2* __restrict__ q16,  uint2* __restrict__ k16,
             uint2* __restrict__ wq16, uint2* __restrict__ wk16,
             uint2* __restrict__ wv16, uint2* __restrict__ w116,
             uint2* __restrict__ w216)
{
    const int bx = blockIdx.x;
    const float4* src; uint2* dst; int off;
    if      (bx <  4096) { src = q;  dst = q16;  off = bx; }
    else if (bx <  8192) { src = k;  dst = k16;  off = bx - 4096; }
    else if (bx <  9216) { src = wq; dst = wq16; off = bx - 8192; }
    else if (bx < 10240) { src = wk; dst = wk16; off = bx - 9216; }
    else if (bx < 11264) { src = wv; dst = wv16; off = bx - 10240; }
    else if (bx < 15360) { src = w1; dst = w116; off = bx - 11264; }
    else                 { src = w2; dst = w216; off = bx - 15360; }
    const int i = off * 256 + threadIdx.x;
    float4 v = src[i];
    uint2 o;
    o.x = packh2(v.x, v.y);
    o.y = packh2(v.z, v.w);
    dst[i] = o;
}

// ---------------- fp16 GEMM, NT, 128x128 tile, cp.async 3-stage ----------
// C[m,n] = sum_k A[m,k]*B[n,k]. 8 warps 2m x 4n, warp tile 64x32, KC=32.
// EPI: 0 = +bias -> fp16; 1 = gelu(+bias) -> fp16; 2 = +bias+res -> fp32
#define KC32   32
#define HPW    40                        // pitch 40 halves = 80B = 5*16
#define ABYTES (128 * HPW * 2)           // 10240 B per operand tile
#define STAGEB (2 * ABYTES)              // 20480 B per stage (A + B)
#define NSTG   3
#define GSMEM  (NSTG * STAGEB)           // 61440 B dynamic smem

template<int EPI>
__global__ __launch_bounds__(256, 2)
void gemm16(const __half* __restrict__ A, const __half* __restrict__ Bm,
            const float* __restrict__ bias, void* __restrict__ Cout,
            const float* __restrict__ res, int M, int N, int K)
{
    extern __shared__ char smem[];
    const uint32_t sbase = (uint32_t)__cvta_generic_to_shared(smem);

    const int tid  = threadIdx.x;
    const int m0   = blockIdx.y * 128;
    const int n0   = blockIdx.x * 128;
    const int lane = tid & 31;
    const int w    = tid >> 5;
    const int wm   = (w >> 2) * 64;      // 0 or 64
    const int wn   = (w & 3) * 32;       // 0..96
    const int g    = lane >> 2;
    const int t    = lane & 3;

    float acc[4][4][4];
    #pragma unroll
    for (int i = 0; i < 4; i++)
        #pragma unroll
        for (int j = 0; j < 4; j++)
            #pragma unroll
            for (int u = 0; u < 4; u++) acc[i][j][u] = 0.f;

    const uint32_t a_frag = sbase + (((uint32_t)(wm + (lane & 15))) * HPW + ((lane >> 4) * 8)) * 2;
    const uint32_t b_frag = sbase + ABYTES + (((uint32_t)(wn + (lane & 7))) * HPW + ((lane >> 3) * 8)) * 2;

    // cp.async staging: 256 threads cover 64 rows x 4 groups; 2 row-batches each op
    const int srow = tid >> 2;           // 0..63
    const int sgrp = tid & 3;            // 16B group
    const uint32_t sdst = sbase + ((uint32_t)(srow * HPW + sgrp * 8)) * 2;
    const __half* gA = A  + (size_t)(m0 + srow) * K + sgrp * 8;
    const __half* gB = Bm + (size_t)(n0 + srow) * K + sgrp * 8;

    auto issue = [&](int c) {
        const uint32_t so = (uint32_t)(c % NSTG) * STAGEB;
        const int k0 = c * KC32;
        CP_ASYNC16(sdst + so,                       gA + k0);
        CP_ASYNC16(sdst + so + 64 * HPW * 2,        gA + (size_t)64 * K + k0);
        CP_ASYNC16(sdst + so + ABYTES,              gB + k0);
        CP_ASYNC16(sdst + so + ABYTES + 64 * HPW * 2, gB + (size_t)64 * K + k0);
    };
    auto compute = [&](int st) {
        const uint32_t bo = (uint32_t)st * STAGEB;
        unsigned bq[4][4];
        #pragma unroll
        for (int nt = 0; nt < 4; nt++)
            LDSM_X4(bq[nt][0], bq[nt][1], bq[nt][2], bq[nt][3],
                    b_frag + bo + nt * (8 * HPW * 2));
        #pragma unroll
        for (int kh = 0; kh < 2; kh++) {
            unsigned aq[4][4];
            #pragma unroll
            for (int mt = 0; mt < 4; mt++)
                LDSM_X4(aq[mt][0], aq[mt][1], aq[mt][2], aq[mt][3],
                        a_frag + bo + mt * (16 * HPW * 2) + kh * 32);
            #pragma unroll
            for (int mt = 0; mt < 4; mt++)
                #pragma unroll
                for (int nt = 0; nt < 4; nt++)
                    mma_f16(acc[mt][nt], aq[mt][0], aq[mt][1], aq[mt][2], aq[mt][3],
                            bq[nt][kh * 2], bq[nt][kh * 2 + 1]);
        }
    };

    const int NC = K / KC32;
    issue(0); CP_COMMIT();
    if (NC > 1) issue(1);
    CP_COMMIT();
    for (int c = 0; c < NC; c++) {
        CP_WAIT1();                 // stage c landed
        __syncthreads();            // all warps done with stage (c-1)%NSTG too
        if (c + 2 < NC) issue(c + 2);
        CP_COMMIT();                // uniform group accounting
        compute(c % NSTG);
    }

    // epilogue
    #pragma unroll
    for (int mt = 0; mt < 4; mt++) {
        #pragma unroll
        for (int half = 0; half < 2; half++) {
            const int row = m0 + wm + mt * 16 + g + half * 8;
            #pragma unroll
            for (int nt = 0; nt < 4; nt++) {
                const int col = n0 + wn + nt * 8 + 2 * t;
                float v0 = acc[mt][nt][half * 2 + 0] + bias[col];
                float v1 = acc[mt][nt][half * 2 + 1] + bias[col + 1];
                if (EPI == 1) {
                    v0 = 0.5f * v0 * (1.0f + erff(v0 * 0.70710678118654752f));
                    v1 = 0.5f * v1 * (1.0f + erff(v1 * 0.70710678118654752f));
                }
                if (EPI == 2) {
                    v0 += res[(size_t)row * N + col];
                    v1 += res[(size_t)row * N + col + 1];
                    float2 o; o.x = v0; o.y = v1;
                    *(float2*)&((float*)Cout)[(size_t)row * N + col] = o;
                } else {
                    *(unsigned*)&((__half*)Cout)[(size_t)row * N + col] = packh2(v0, v1);
                }
            }
        }
    }
}

// ---------------- fp16 tensor-core causal flash attention (R11) ----------
#define AP 72
#define ATILE (64 * AP)   // halves per tile

__global__ __launch_bounds__(128, 3)
void attn_tc(const __half* __restrict__ Q, const __half* __restrict__ K,
             const __half* __restrict__ V, float* __restrict__ O,
             const int* __restrict__ use_mask)
{
    __shared__ __half Ks[2][ATILE];
    __shared__ __half Vs[2][ATILE];

    const int tid  = threadIdx.x;
    const int lane = tid & 31;
    const int w    = tid >> 5;
    const int g    = lane >> 2;
    const int t    = lane & 3;
    const int qb   = (gridDim.x - 1) - blockIdx.x;
    const int h    = blockIdx.y;
    const int b    = blockIdx.z;
    const int q0   = qb * 64;
    const int causal = use_mask[0];
    const int row0 = q0 + w * 16 + g;

    unsigned qf[4][4];
    {
        const __half* qp  = Q + ((size_t)(b * S_ + row0)) * DM + h * DH;
        const __half* qp8 = qp + 8 * DM;
        #pragma unroll
        for (int ks = 0; ks < 4; ks++) {
            const int c = ks * 16 + 2 * t;
            qf[ks][0] = *(const unsigned*)&qp [c];
            qf[ks][1] = *(const unsigned*)&qp8[c];
            qf[ks][2] = *(const unsigned*)&qp [c + 8];
            qf[ks][3] = *(const unsigned*)&qp8[c + 8];
        }
    }

    const uint32_t sK = (uint32_t)__cvta_generic_to_shared(&Ks[0][0]);
    const uint32_t sV = (uint32_t)__cvta_generic_to_shared(&Vs[0][0]);
    const uint32_t k_frag = sK + (((uint32_t)(lane & 7))  * AP + ((lane >> 3) * 8)) * 2;
    const uint32_t v_frag = sV + (((uint32_t)(lane & 15)) * AP + ((lane >> 4) * 8)) * 2;

    const int sr = tid >> 3;
    const int sg = tid & 7;
    const uint32_t kdst = sK + ((uint32_t)(sr * AP + sg * 8)) * 2;
    const uint32_t vdst = sV + ((uint32_t)(sr * AP + sg * 8)) * 2;
    const __half* ksrc = K + ((size_t)(b * S_) + sr) * DM + h * DH + sg * 8;
    const __half* vsrc = V + ((size_t)(b * S_) + sr) * DM + h * DH + sg * 8;

    auto issue_tile = [&](int kb, int buf) {
        const uint32_t bo = (uint32_t)buf * (ATILE * 2);
        const size_t go = (size_t)(kb * 64) * DM;
        #pragma unroll
        for (int i = 0; i < 4; i++) {
            const uint32_t so = (uint32_t)(i * 16 * AP) * 2;
            const size_t gg = go + (size_t)(i * 16) * DM;
            CP_ASYNC16(kdst + bo + so, ksrc + gg);
            CP_ASYNC16(vdst + bo + so, vsrc + gg);
        }
    };

    float m0 = -INFINITY, m1 = -INFINITY, l0 = 0.f, l1 = 0.f;
    float oacc[8][4];
    #pragma unroll
    for (int nt = 0; nt < 8; nt++)
        #pragma unroll
        for (int u = 0; u < 4; u++) oacc[nt][u] = 0.f;

    const int nkb = causal ? (qb + 1) : (S_ / 64);

    issue_tile(0, 0);
    CP_COMMIT();
    if (nkb > 1) issue_tile(1, 1);
    CP_COMMIT();

    for (int kb = 0; kb < nkb; kb++) {
        const int buf = kb & 1;
        CP_WAIT1();
        __syncthreads();

        const uint32_t bo = (uint32_t)buf * (ATILE * 2);

        float sa[8][4];
        #pragma unroll
        for (int nt = 0; nt < 8; nt++)
            #pragma unroll
            for (int u = 0; u < 4; u++) sa[nt][u] = 0.f;

        #pragma unroll
        for (int nt = 0; nt < 8; nt++) {
            unsigned kq[8];
            LDSM_X4(kq[0], kq[1], kq[2], kq[3], k_frag + bo + (nt * 8 * AP) * 2);
            LDSM_X4(kq[4], kq[5], kq[6], kq[7], k_frag + bo + (nt * 8 * AP) * 2 + 64);
            #pragma unroll
            for (int ks = 0; ks < 4; ks++)
                mma_f16(sa[nt], qf[ks][0], qf[ks][1], qf[ks][2], qf[ks][3],
                        kq[ks * 2], kq[ks * 2 + 1]);
        }

        const bool mask_tile = causal && (kb == qb);
        float smax0 = -INFINITY, smax1 = -INFINITY;
        #pragma unroll
        for (int nt = 0; nt < 8; nt++) {
            const int col = kb * 64 + nt * 8 + 2 * t;
            sa[nt][0] *= 0.125f; sa[nt][1] *= 0.125f;
            sa[nt][2] *= 0.125f; sa[nt][3] *= 0.125f;
            if (mask_tile) {
                if (col     > row0)     sa[nt][0] = -1e9f;
                if (col + 1 > row0)     sa[nt][1] = -1e9f;
                if (col     > row0 + 8) sa[nt][2] = -1e9f;
                if (col + 1 > row0 + 8) sa[nt][3] = -1e9f;
            }
            smax0 = fmaxf(smax0, fmaxf(sa[nt][0], sa[nt][1]));
            smax1 = fmaxf(smax1, fmaxf(sa[nt][2], sa[nt][3]));
        }
        smax0 = fmaxf(smax0, __shfl_xor_sync(0xffffffffu, smax0, 1));
        smax0 = fmaxf(smax0, __shfl_xor_sync(0xffffffffu, smax0, 2));
        smax1 = fmaxf(smax1, __shfl_xor_sync(0xffffffffu, smax1, 1));
        smax1 = fmaxf(smax1, __shfl_xor_sync(0xffffffffu, smax1, 2));

        const float m0n = fmaxf(m0, smax0);
        const float m1n = fmaxf(m1, smax1);
        const float cr0 = __expf(m0 - m0n);
        const float cr1 = __expf(m1 - m1n);
        m0 = m0n; m1 = m1n;

        float ls0 = 0.f, ls1 = 0.f;
        #pragma unroll
        for (int nt = 0; nt < 8; nt++) {
            sa[nt][0] = __expf(sa[nt][0] - m0n);
            sa[nt][1] = __expf(sa[nt][1] - m0n);
            sa[nt][2] = __expf(sa[nt][2] - m1n);
            sa[nt][3] = __expf(sa[nt][3] - m1n);
            ls0 += sa[nt][0] + sa[nt][1];
            ls1 += sa[nt][2] + sa[nt][3];
        }
        ls0 += __shfl_xor_sync(0xffffffffu, ls0, 1);
        ls0 += __shfl_xor_sync(0xffffffffu, ls0, 2);
        ls1 += __shfl_xor_sync(0xffffffffu, ls1, 1);
        ls1 += __shfl_xor_sync(0xffffffffu, ls1, 2);
        l0 = l0 * cr0 + ls0;
        l1 = l1 * cr1 + ls1;

        #pragma unroll
        for (int nt = 0; nt < 8; nt++) {
            oacc[nt][0] *= cr0; oacc[nt][1] *= cr0;
            oacc[nt][2] *= cr1; oacc[nt][3] *= cr1;
        }

        #pragma unroll
        for (int ks = 0; ks < 4; ks++) {
            const unsigned a0 = packh2(sa[2*ks  ][0], sa[2*ks  ][1]);
            const unsigned a1 = packh2(sa[2*ks  ][2], sa[2*ks  ][3]);
            const unsigned a2 = packh2(sa[2*ks+1][0], sa[2*ks+1][1]);
            const unsigned a3 = packh2(sa[2*ks+1][2], sa[2*ks+1][3]);
            #pragma unroll
            for (int dg = 0; dg < 4; dg++) {
                unsigned v0, v1, v2, v3;
                LDSM_X4T(v0, v1, v2, v3, v_frag + bo + (ks * 16 * AP + dg * 16) * 2);
                mma_f16(oacc[2*dg    ], a0, a1, a2, a3, v0, v1);
                mma_f16(oacc[2*dg + 1], a0, a1, a2, a3, v2, v3);
            }
        }

        __syncthreads();
        if (kb + 2 < nkb) issue_tile(kb + 2, buf);
        CP_COMMIT();
    }

    const float inv0 = 1.f / l0;
    const float inv1 = 1.f / l1;
    float* op = O + ((size_t)(b * S_ + row0)) * DM + h * DH;
    #pragma unroll
    for (int nt = 0; nt < 8; nt++) {
        float2 v;
        v.x = oacc[nt][0] * inv0; v.y = oacc[nt][1] * inv0;
        *(float2*)&op[nt * 8 + 2 * t] = v;
        v.x = oacc[nt][2] * inv1; v.y = oacc[nt][3] * inv1;
        *(float2*)&op[(size_t)8 * DM + nt * 8 + 2 * t] = v;
    }
}

// ---------------- residual add + layernorm (fp32 out + fp16 copy) --------
__global__ __launch_bounds__(256)
void ln_kernel(const float* __restrict__ att, const float* __restrict__ resid,
               const float* __restrict__ g, const float* __restrict__ bt,
               float* __restrict__ xout, __half* __restrict__ xh)
{
    const int row = blockIdx.x;
    const int tid = threadIdx.x;

    float4 a = *(const float4*)&att  [(size_t)row * DM + tid * 4];
    float4 r = *(const float4*)&resid[(size_t)row * DM + tid * 4];
    float4 v;
    v.x = a.x + r.x; v.y = a.y + r.y; v.z = a.z + r.z; v.w = a.w + r.w;

    float s1 = v.x + v.y + v.z + v.w;
    float s2 = v.x*v.x + v.y*v.y + v.z*v.z + v.w*v.w;

    __shared__ float sh1[8], sh2[8];
    #pragma unroll
    for (int o = 16; o > 0; o >>= 1) {
        s1 += __shfl_xor_sync(0xffffffffu, s1, o);
        s2 += __shfl_xor_sync(0xffffffffu, s2, o);
    }
    if ((tid & 31) == 0) { sh1[tid >> 5] = s1; sh2[tid >> 5] = s2; }
    __syncthreads();
    float t1 = 0.f, t2 = 0.f;
    #pragma unroll
    for (int i = 0; i < 8; i++) { t1 += sh1[i]; t2 += sh2[i]; }

    const float mu  = t1 * (1.0f / DM);
    const float var = t2 * (1.0f / DM) - mu * mu;
    const float rs  = rsqrtf(var + 1e-5f);

    float4 gg = *(const float4*)&g [tid * 4];
    float4 bb = *(const float4*)&bt[tid * 4];
    float4 o;
    o.x = (v.x - mu) * rs * gg.x + bb.x;
    o.y = (v.y - mu) * rs * gg.y + bb.y;
    o.z = (v.z - mu) * rs * gg.z + bb.z;
    o.w = (v.w - mu) * rs * gg.w + bb.w;
    *(float4*)&xout[(size_t)row * DM + tid * 4] = o;
    uint2 hh;
    hh.x = packh2(o.x, o.y);
    hh.y = packh2(o.z, o.w);
    *(uint2*)&xh[(size_t)row * DM + tid * 4] = hh;
}

// ---------------- launch ---------------------------------------------------
extern "C" void kernel_launch(void* const* d_in, const int* in_sizes, int n_in,
                              void* d_out, int out_size)
{
    const float* q    = (const float*)d_in[0];
    const float* k    = (const float*)d_in[1];
    const float* Wq   = (const float*)d_in[2];
    const float* bq   = (const float*)d_in[3];
    const float* Wk   = (const float*)d_in[4];
    const float* bk   = (const float*)d_in[5];
    const float* Wv   = (const float*)d_in[6];
    const float* bv   = (const float*)d_in[7];
    const float* W1   = (const float*)d_in[8];
    const float* b1   = (const float*)d_in[9];
    const float* W2   = (const float*)d_in[10];
    const float* b2   = (const float*)d_in[11];
    const float* ln_g = (const float*)d_in[12];
    const float* ln_b = (const float*)d_in[13];
    const int*   msk  = (const int*)d_in[14];

    __half *q16, *k16, *wq16, *wk16, *wv16, *w116, *w216, *Qh, *Kh, *Vh, *Xh, *Hh;
    float *Ab, *Xb;
    cudaGetSymbolAddress((void**)&q16,  g_q16);
    cudaGetSymbolAddress((void**)&k16,  g_k16);
    cudaGetSymbolAddress((void**)&wq16, g_wq16);
    cudaGetSymbolAddress((void**)&wk16, g_wk16);
    cudaGetSymbolAddress((void**)&wv16, g_wv16);
    cudaGetSymbolAddress((void**)&w116, g_w116);
    cudaGetSymbolAddress((void**)&w216, g_w216);
    cudaGetSymbolAddress((void**)&Qh,   g_Qh);
    cudaGetSymbolAddress((void**)&Kh,   g_Kh);
    cudaGetSymbolAddress((void**)&Vh,   g_Vh);
    cudaGetSymbolAddress((void**)&Xh,   g_Xh);
    cudaGetSymbolAddress((void**)&Hh,   g_Hh);
    cudaGetSymbolAddress((void**)&Ab,   g_att);
    cudaGetSymbolAddress((void**)&Xb,   g_x);

    cudaFuncSetAttribute(gemm16<0>, cudaFuncAttributeMaxDynamicSharedMemorySize, GSMEM);
    cudaFuncSetAttribute(gemm16<1>, cudaFuncAttributeMaxDynamicSharedMemorySize, GSMEM);
    cudaFuncSetAttribute(gemm16<2>, cudaFuncAttributeMaxDynamicSharedMemorySize, GSMEM);

    // fused fp32 -> fp16 conversion pass
    f2h_all<<<19456, 256>>>((const float4*)q,  (const float4*)k,
                            (const float4*)Wq, (const float4*)Wk,
                            (const float4*)Wv, (const float4*)W1,
                            (const float4*)W2,
                            (uint2*)q16, (uint2*)k16, (uint2*)wq16,
                            (uint2*)wk16, (uint2*)wv16, (uint2*)w116,
                            (uint2*)w216);

    // QKV projections (fp16 out)
    gemm16<0><<<dim3(DM / 128, MTOK / 128), 256, GSMEM>>>(q16, wq16, bq, Qh, nullptr, MTOK, DM, DM);
    gemm16<0><<<dim3(DM / 128, MTOK / 128), 256, GSMEM>>>(k16, wk16, bk, Kh, nullptr, MTOK, DM, DM);
    gemm16<0><<<dim3(DM / 128, MTOK / 128), 256, GSMEM>>>(k16, wv16, bv, Vh, nullptr, MTOK, DM, DM);

    // causal attention (fp16 in, fp32 out)
    attn_tc<<<dim3(S_ / 64, H_, B_), 128>>>(Qh, Kh, Vh, Ab, msk);

    // residual + layernorm (fp32 + fp16 outputs)
    ln_kernel<<<MTOK, 256>>>(Ab, q, ln_g, ln_b, Xb, Xh);

    // FFN
    gemm16<1><<<dim3(DFF / 128, MTOK / 128), 256, GSMEM>>>(Xh, w116, b1, Hh, nullptr, MTOK, DFF, DM);
    gemm16<2><<<dim3(DM / 128, MTOK / 128), 256, GSMEM>>>(Hh, w216, b2, d_out, Xb, MTOK, DM, DFF);
}